// round 6
// baseline (speedup 1.0000x reference)
#include <cuda_runtime.h>
#include <cuda_bf16.h>
#include <math.h>

#define NTOK 8192
#define DIM  1024
#define KT   32          // k-tile depth (bf16 elements)
#define BPADE 40         // smem row stride in elements (80B = 5*16B)
#define ARR_BYTES 10240  // 128 * 40 * 2
#define STAGE_BYTES 40960
#define NSTAGE 3
#define SMEM_TOTAL (NSTAGE * STAGE_BYTES)
#define NTHR 512

// ---------------------------------------------------------------------------
// Scratch (static device globals)
// ---------------------------------------------------------------------------
__device__ __nv_bfloat16 g_xh[(size_t)NTOK * DIM], g_xl[(size_t)NTOK * DIM];
__device__ __nv_bfloat16 g_Wh[3][(size_t)DIM * DIM], g_Wl[3][(size_t)DIM * DIM];
__device__ __nv_bfloat16 g_Qh[(size_t)NTOK * DIM], g_Ql[(size_t)NTOK * DIM];
__device__ __nv_bfloat16 g_Kh[(size_t)NTOK * DIM], g_Kl[(size_t)NTOK * DIM];
__device__ __nv_bfloat16 g_Vth[(size_t)DIM * NTOK], g_Vtl[(size_t)DIM * NTOK];  // [dim][token]
__device__ __nv_bfloat16 g_Ph[(size_t)NTOK * NTOK], g_Pl[(size_t)NTOK * NTOK];  // unnormalized
__device__ float g_S[(size_t)NTOK * NTOK];
__device__ float g_invl[NTOK];

// ---------------------------------------------------------------------------
// helpers
// ---------------------------------------------------------------------------
__device__ __forceinline__ unsigned smem_u32(const void* p) {
    return (unsigned)__cvta_generic_to_shared(p);
}
__device__ __forceinline__ void cpa16(unsigned s, const void* g) {
    asm volatile("cp.async.cg.shared.global [%0],[%1],16;" :: "r"(s), "l"(g));
}
__device__ __forceinline__ void cpa_commit() {
    asm volatile("cp.async.commit_group;" ::: "memory");
}
__device__ __forceinline__ void cpa_wait0() {
    asm volatile("cp.async.wait_group 0;" ::: "memory");
}
__device__ __forceinline__ void cpa_wait1() {
    asm volatile("cp.async.wait_group 1;" ::: "memory");
}
__device__ __forceinline__ void ldsm4(unsigned r[4], unsigned addr) {
    asm volatile("ldmatrix.sync.aligned.m8n8.x4.shared.b16 {%0,%1,%2,%3},[%4];"
                 : "=r"(r[0]), "=r"(r[1]), "=r"(r[2]), "=r"(r[3]) : "r"(addr));
}
__device__ __forceinline__ void mma_bf16(float c[4], const unsigned a[4], const unsigned b[2]) {
    asm volatile("mma.sync.aligned.m16n8k16.row.col.f32.bf16.bf16.f32 "
                 "{%0,%1,%2,%3},{%4,%5,%6,%7},{%8,%9},{%0,%1,%2,%3};"
                 : "+f"(c[0]), "+f"(c[1]), "+f"(c[2]), "+f"(c[3])
                 : "r"(a[0]), "r"(a[1]), "r"(a[2]), "r"(a[3]), "r"(b[0]), "r"(b[1]));
}

// ---------------------------------------------------------------------------
// one 128x128xKT tile of split-MMA; warp tile 32x32 (16 warps)
// ---------------------------------------------------------------------------
__device__ __forceinline__ void mma_tile(const char* sb, int lane, int wm, int wn,
                                         float acc[2][4][4])
{
    const __nv_bfloat16 (*Ah)[BPADE] = (const __nv_bfloat16(*)[BPADE])(sb);
    const __nv_bfloat16 (*Al)[BPADE] = (const __nv_bfloat16(*)[BPADE])(sb + ARR_BYTES);
    const __nv_bfloat16 (*Bh)[BPADE] = (const __nv_bfloat16(*)[BPADE])(sb + 2 * ARR_BYTES);
    const __nv_bfloat16 (*Bl)[BPADE] = (const __nv_bfloat16(*)[BPADE])(sb + 3 * ARR_BYTES);

#pragma unroll
    for (int kk = 0; kk < KT; kk += 16) {
        unsigned ah[2][4], al[2][4], bh[2][4], bl[2][4];
        int arow = (lane & 7) + ((lane >> 3) & 1) * 8;
        int acol = kk + (lane >> 4) * 8;
#pragma unroll
        for (int mi = 0; mi < 2; mi++) {
            int r = wm * 32 + mi * 16 + arow;
            ldsm4(ah[mi], smem_u32(&Ah[r][acol]));
            ldsm4(al[mi], smem_u32(&Al[r][acol]));
        }
        int brow = (lane & 7) + ((lane >> 4) & 1) * 8;
        int bcol = kk + ((lane >> 3) & 1) * 8;
#pragma unroll
        for (int p = 0; p < 2; p++) {
            int n = wn * 32 + p * 16 + brow;
            ldsm4(bh[p], smem_u32(&Bh[n][bcol]));
            ldsm4(bl[p], smem_u32(&Bl[n][bcol]));
        }
#pragma unroll
        for (int mi = 0; mi < 2; mi++)
#pragma unroll
            for (int ni = 0; ni < 4; ni++) {
                const unsigned* bhp = &bh[ni >> 1][(ni & 1) * 2];
                const unsigned* blp = &bl[ni >> 1][(ni & 1) * 2];
                mma_bf16(acc[mi][ni], ah[mi], bhp);
                mma_bf16(acc[mi][ni], ah[mi], blp);
                mma_bf16(acc[mi][ni], al[mi], bhp);
            }
    }
}

// ---------------------------------------------------------------------------
// stage loader: 4 cp.async x 16B per thread (512 threads cover 128 rows x 4 arrays)
// ---------------------------------------------------------------------------
__device__ __forceinline__ void load_stage(
    unsigned st,
    const __nv_bfloat16* gAh, const __nv_bfloat16* gAl,
    const __nv_bfloat16* gBh, const __nv_bfloat16* gBl, int koff)
{
    cpa16(st, gAh + koff);
    cpa16(st + ARR_BYTES, gAl + koff);
    cpa16(st + 2 * ARR_BYTES, gBh + koff);
    cpa16(st + 3 * ARR_BYTES, gBl + koff);
}

// 3-stage pipelined mainloop. A rows at rowBase, B rows at colBase, k-contig.
template <int KITERS>
__device__ __forceinline__ void gemm_core(
    const __nv_bfloat16* __restrict__ Agh, const __nv_bfloat16* __restrict__ Agl, int sA,
    const __nv_bfloat16* __restrict__ Bgh, const __nv_bfloat16* __restrict__ Bgl, int sB,
    int rowBase, int colBase, char* smem, float acc[2][4][4])
{
    int tid = threadIdx.x;
    int row = tid >> 2, ck = (tid & 3) * 8;

    const __nv_bfloat16* gAh = Agh + (size_t)(rowBase + row) * sA + ck;
    const __nv_bfloat16* gAl = Agl + (size_t)(rowBase + row) * sA + ck;
    const __nv_bfloat16* gBh = Bgh + (size_t)(colBase + row) * sB + ck;
    const __nv_bfloat16* gBl = Bgl + (size_t)(colBase + row) * sB + ck;

    unsigned s0 = smem_u32(smem) + (row * BPADE + ck) * 2;
    int lane = tid & 31, warp = tid >> 5, wm = warp >> 2, wn = warp & 3;

    // prologue: stages 0 and 1
    load_stage(s0, gAh, gAl, gBh, gBl, 0);
    cpa_commit();
    load_stage(s0 + STAGE_BYTES, gAh, gAl, gBh, gBl, KT);
    cpa_commit();

    for (int it = 0; it < KITERS; it++) {
        if (it == KITERS - 1) cpa_wait0(); else cpa_wait1();
        __syncthreads();
        if (it + 2 < KITERS) {
            load_stage(s0 + ((it + 2) % NSTAGE) * STAGE_BYTES,
                       gAh, gAl, gBh, gBl, (it + 2) * KT);
            cpa_commit();
        }
        mma_tile(smem + (it % NSTAGE) * STAGE_BYTES, lane, wm, wn, acc);
    }
}

// ---------------------------------------------------------------------------
// elementwise fp32 -> bf16 hi/lo split
// ---------------------------------------------------------------------------
__global__ __launch_bounds__(256) void split_kernel(
    const float* __restrict__ src, __nv_bfloat16* __restrict__ h,
    __nv_bfloat16* __restrict__ l, int n)
{
    int i = (blockIdx.x * 256 + threadIdx.x) * 4;
    if (i >= n) return;
    float4 v = *(const float4*)(src + i);
    float f[4] = {v.x, v.y, v.z, v.w};
    __nv_bfloat16 hh[4], ll[4];
#pragma unroll
    for (int j = 0; j < 4; j++) {
        hh[j] = __float2bfloat16(f[j]);
        ll[j] = __float2bfloat16(f[j] - __bfloat162float(hh[j]));
    }
    ((__nv_bfloat162*)(h + i))[0] = __halves2bfloat162(hh[0], hh[1]);
    ((__nv_bfloat162*)(h + i))[1] = __halves2bfloat162(hh[2], hh[3]);
    ((__nv_bfloat162*)(l + i))[0] = __halves2bfloat162(ll[0], ll[1]);
    ((__nv_bfloat162*)(l + i))[1] = __halves2bfloat162(ll[2], ll[3]);
}

// ---------------------------------------------------------------------------
// QKV: out = x @ W^T + b, split-stored. z=2 (V) stored transposed [dim][token].
// grid (64, 8, 3), block 512
// ---------------------------------------------------------------------------
__global__ __launch_bounds__(NTHR, 1) void qkv_mma(
    const float* __restrict__ bq, const float* __restrict__ bk,
    const float* __restrict__ bv)
{
    extern __shared__ char smem[];
    int z = blockIdx.z;
    const float* bias = (z == 0) ? bq : (z == 1) ? bk : bv;

    int tid = threadIdx.x, lane = tid & 31, warp = tid >> 5;
    int wm = warp >> 2, wn = warp & 3;
    int rowBase = blockIdx.x * 128, colBase = blockIdx.y * 128;

    float acc[2][4][4] = {};
    gemm_core<DIM / KT>(g_xh, g_xl, DIM, g_Wh[z], g_Wl[z], DIM,
                        rowBase, colBase, smem, acc);

    if (z < 2) {
        __nv_bfloat16* oh = (z == 0) ? g_Qh : g_Kh;
        __nv_bfloat16* ol = (z == 0) ? g_Ql : g_Kl;
#pragma unroll
        for (int mi = 0; mi < 2; mi++)
#pragma unroll
            for (int ni = 0; ni < 4; ni++) {
                int r = rowBase + wm * 32 + mi * 16 + (lane >> 2);
                int c = colBase + wn * 32 + ni * 8 + (lane & 3) * 2;
                float b0 = bias[c], b1 = bias[c + 1];
#pragma unroll
                for (int hr = 0; hr < 2; hr++) {
                    float v0 = acc[mi][ni][hr * 2] + b0;
                    float v1 = acc[mi][ni][hr * 2 + 1] + b1;
                    __nv_bfloat16 h0 = __float2bfloat16(v0), h1 = __float2bfloat16(v1);
                    size_t o = (size_t)(r + hr * 8) * DIM + c;
                    *(__nv_bfloat162*)(oh + o) = __halves2bfloat162(h0, h1);
                    *(__nv_bfloat162*)(ol + o) = __halves2bfloat162(
                        __float2bfloat16(v0 - __bfloat162float(h0)),
                        __float2bfloat16(v1 - __bfloat162float(h1)));
                }
            }
    } else {
        // V: transpose via smem, store [dim][token]
        __syncthreads();  // done with mainloop buffers
        __nv_bfloat16 (*Th)[136] = (__nv_bfloat16(*)[136])(smem);
        __nv_bfloat16 (*Tl)[136] = (__nv_bfloat16(*)[136])(smem + 128 * 136 * 2);
#pragma unroll
        for (int mi = 0; mi < 2; mi++)
#pragma unroll
            for (int ni = 0; ni < 4; ni++) {
                int rL = wm * 32 + mi * 16 + (lane >> 2);
                int cL = wn * 32 + ni * 8 + (lane & 3) * 2;
                float b0 = bias[colBase + cL], b1 = bias[colBase + cL + 1];
#pragma unroll
                for (int hr = 0; hr < 2; hr++) {
                    float v0 = acc[mi][ni][hr * 2] + b0;
                    float v1 = acc[mi][ni][hr * 2 + 1] + b1;
                    __nv_bfloat16 h0 = __float2bfloat16(v0), h1 = __float2bfloat16(v1);
                    Th[cL][rL + hr * 8] = h0;
                    Th[cL + 1][rL + hr * 8] = h1;
                    Tl[cL][rL + hr * 8] = __float2bfloat16(v0 - __bfloat162float(h0));
                    Tl[cL + 1][rL + hr * 8] = __float2bfloat16(v1 - __bfloat162float(h1));
                }
            }
        __syncthreads();
#pragma unroll
        for (int j = 0; j < 4; j++) {
            int idx = j * NTHR + tid;
            int cRow = idx >> 4, ch = (idx & 15) * 8;
            float4 vh = *(float4*)&Th[cRow][ch];
            float4 vl = *(float4*)&Tl[cRow][ch];
            size_t o = (size_t)(colBase + cRow) * NTOK + rowBase + ch;
            *(float4*)(g_Vth + o) = vh;
            *(float4*)(g_Vtl + o) = vl;
        }
    }
}

// ---------------------------------------------------------------------------
// Scores: S = (Q @ K^T)/32 - |dt|/86400.  grid (64, 64), block 512
// ---------------------------------------------------------------------------
__global__ __launch_bounds__(NTHR, 1) void scores_mma(const float* __restrict__ ts)
{
    extern __shared__ char smem[];
    int tid = threadIdx.x, lane = tid & 31, warp = tid >> 5;
    int wm = warp >> 2, wn = warp & 3;
    int rowBase = blockIdx.x * 128, colBase = blockIdx.y * 128;

    float acc[2][4][4] = {};
    gemm_core<DIM / KT>(g_Qh, g_Ql, DIM, g_Kh, g_Kl, DIM,
                        rowBase, colBase, smem, acc);

    const float inv_scale = 1.0f / 32.0f;
    const float inv_T = 1.0f / 86400.0f;

#pragma unroll
    for (int mi = 0; mi < 2; mi++) {
        int r = rowBase + wm * 32 + mi * 16 + (lane >> 2);
        float t_r0 = ts[r], t_r1 = ts[r + 8];
#pragma unroll
        for (int ni = 0; ni < 4; ni++) {
            int c = colBase + wn * 32 + ni * 8 + (lane & 3) * 2;
            float tc0 = ts[c], tc1 = ts[c + 1];
            float b00 = -fabsf(t_r0 - tc0) * inv_T;
            float b01 = -fabsf(t_r0 - tc1) * inv_T;
            float b10 = -fabsf(t_r1 - tc0) * inv_T;
            float b11 = -fabsf(t_r1 - tc1) * inv_T;
            *(float2*)(g_S + (size_t)r * NTOK + c) =
                make_float2(acc[mi][ni][0] * inv_scale + b00, acc[mi][ni][1] * inv_scale + b01);
            *(float2*)(g_S + (size_t)(r + 8) * NTOK + c) =
                make_float2(acc[mi][ni][2] * inv_scale + b10, acc[mi][ni][3] * inv_scale + b11);
        }
    }
}

// ---------------------------------------------------------------------------
// Row softmax: S -> P~ = exp(S - m) (unnormalized, bf16 hi/lo); 1/l saved.
// grid NTOK, block 256
// ---------------------------------------------------------------------------
__global__ __launch_bounds__(256) void softmax_kernel()
{
    __shared__ float sred[256];
    __shared__ float s_m, s_invl;

    int row = blockIdx.x;
    int tid = threadIdx.x;
    const float* Srow = g_S + (size_t)row * NTOK;

    // pass 1: max
    float m = -INFINITY;
    for (int j = tid * 4; j < NTOK; j += 1024) {
        float4 v = *(const float4*)(Srow + j);
        m = fmaxf(m, fmaxf(fmaxf(v.x, v.y), fmaxf(v.z, v.w)));
    }
    sred[tid] = m;
    __syncthreads();
    for (int off = 128; off > 0; off >>= 1) {
        if (tid < off) sred[tid] = fmaxf(sred[tid], sred[tid + off]);
        __syncthreads();
    }
    if (tid == 0) s_m = sred[0];
    __syncthreads();
    float mm = s_m;
    __syncthreads();

    // pass 2: exp, store P~, accumulate l
    __nv_bfloat16* Ph = g_Ph + (size_t)row * NTOK;
    __nv_bfloat16* Pl = g_Pl + (size_t)row * NTOK;
    float l = 0.0f;
    for (int j = tid * 4; j < NTOK; j += 1024) {
        float4 v = *(const float4*)(Srow + j);
        float f[4] = {v.x, v.y, v.z, v.w};
        __nv_bfloat16 hh[4], ll[4];
#pragma unroll
        for (int q = 0; q < 4; q++) {
            float p = __expf(f[q] - mm);
            l += p;
            hh[q] = __float2bfloat16(p);
            ll[q] = __float2bfloat16(p - __bfloat162float(hh[q]));
        }
        ((__nv_bfloat162*)(Ph + j))[0] = __halves2bfloat162(hh[0], hh[1]);
        ((__nv_bfloat162*)(Ph + j))[1] = __halves2bfloat162(hh[2], hh[3]);
        ((__nv_bfloat162*)(Pl + j))[0] = __halves2bfloat162(ll[0], ll[1]);
        ((__nv_bfloat162*)(Pl + j))[1] = __halves2bfloat162(ll[2], ll[3]);
    }
    sred[tid] = l;
    __syncthreads();
    for (int off = 128; off > 0; off >>= 1) {
        if (tid < off) sred[tid] += sred[tid + off];
        __syncthreads();
    }
    if (tid == 0) g_invl[row] = 1.0f / sred[0];
}

// ---------------------------------------------------------------------------
// Output: O = diag(1/l) P~ @ V.  grid (64, 8), block 512
// ---------------------------------------------------------------------------
__global__ __launch_bounds__(NTHR, 1) void out_mma(float* __restrict__ O)
{
    extern __shared__ char smem[];
    int tid = threadIdx.x, lane = tid & 31, warp = tid >> 5;
    int wm = warp >> 2, wn = warp & 3;
    int rowBase = blockIdx.x * 128, colBase = blockIdx.y * 128;

    float acc[2][4][4] = {};
    gemm_core<NTOK / KT>(g_Ph, g_Pl, NTOK, g_Vth, g_Vtl, NTOK,
                         rowBase, colBase, smem, acc);

#pragma unroll
    for (int mi = 0; mi < 2; mi++) {
        int r = rowBase + wm * 32 + mi * 16 + (lane >> 2);
        float i0 = g_invl[r], i1 = g_invl[r + 8];
#pragma unroll
        for (int ni = 0; ni < 4; ni++) {
            int c = colBase + wn * 32 + ni * 8 + (lane & 3) * 2;
            *(float2*)(O + (size_t)r * DIM + c) =
                make_float2(acc[mi][ni][0] * i0, acc[mi][ni][1] * i0);
            *(float2*)(O + (size_t)(r + 8) * DIM + c) =
                make_float2(acc[mi][ni][2] * i1, acc[mi][ni][3] * i1);
        }
    }
}

// ---------------------------------------------------------------------------
extern "C" void kernel_launch(void* const* d_in, const int* in_sizes, int n_in,
                              void* d_out, int out_size)
{
    const float* x  = (const float*)d_in[0];
    const float* ts = (const float*)d_in[1];
    const float* Wq = (const float*)d_in[2];
    const float* bq = (const float*)d_in[3];
    const float* Wk = (const float*)d_in[4];
    const float* bk = (const float*)d_in[5];
    const float* Wv = (const float*)d_in[6];
    const float* bv = (const float*)d_in[7];
    float* out = (float*)d_out;

    cudaFuncSetAttribute(qkv_mma,    cudaFuncAttributeMaxDynamicSharedMemorySize, SMEM_TOTAL);
    cudaFuncSetAttribute(scores_mma, cudaFuncAttributeMaxDynamicSharedMemorySize, SMEM_TOTAL);
    cudaFuncSetAttribute(out_mma,    cudaFuncAttributeMaxDynamicSharedMemorySize, SMEM_TOTAL);

    __nv_bfloat16 *xh, *xl, *wh0, *wl0;
    cudaGetSymbolAddress((void**)&xh, g_xh);
    cudaGetSymbolAddress((void**)&xl, g_xl);
    cudaGetSymbolAddress((void**)&wh0, g_Wh);
    cudaGetSymbolAddress((void**)&wl0, g_Wl);

    const size_t ND = (size_t)NTOK * DIM, DD = (size_t)DIM * DIM;
    split_kernel<<<(int)(ND / 1024), 256>>>(x, xh, xl, (int)ND);
    split_kernel<<<(int)(DD / 1024), 256>>>(Wq, wh0,          wl0,          (int)DD);
    split_kernel<<<(int)(DD / 1024), 256>>>(Wk, wh0 + DD,     wl0 + DD,     (int)DD);
    split_kernel<<<(int)(DD / 1024), 256>>>(Wv, wh0 + 2 * DD, wl0 + 2 * DD, (int)DD);

    qkv_mma<<<dim3(NTOK / 128, DIM / 128, 3), NTHR, SMEM_TOTAL>>>(bq, bk, bv);
    scores_mma<<<dim3(NTOK / 128, NTOK / 128), NTHR, SMEM_TOTAL>>>(ts);
    softmax_kernel<<<NTOK, 256>>>();
    out_mma<<<dim3(NTOK / 128, DIM / 128), NTHR, SMEM_TOTAL>>>(out);
}

// round 7
// speedup vs baseline: 1.0122x; 1.0122x over previous
#include <cuda_runtime.h>
#include <cuda_bf16.h>
#include <math.h>

#define NTOK 8192
#define DIM  1024
#define KT   32          // k-tile depth (bf16 elements)
#define BPADE 40         // smem row stride in elements (80B = 5*16B)
#define ARR_BYTES 10240  // 128 * 40 * 2
#define STAGE_BYTES 40960
#define NSTAGE 3
#define SMEM_TOTAL (NSTAGE * STAGE_BYTES)
#define NTHR 512

// ---------------------------------------------------------------------------
// Scratch (static device globals)
// ---------------------------------------------------------------------------
__device__ __nv_bfloat16 g_xh[(size_t)NTOK * DIM], g_xl[(size_t)NTOK * DIM];
__device__ __nv_bfloat16 g_Wh[3][(size_t)DIM * DIM], g_Wl[3][(size_t)DIM * DIM];
__device__ __nv_bfloat16 g_Qh[(size_t)NTOK * DIM], g_Ql[(size_t)NTOK * DIM];
__device__ __nv_bfloat16 g_Kh[(size_t)NTOK * DIM], g_Kl[(size_t)NTOK * DIM];
__device__ __nv_bfloat16 g_Vth[(size_t)DIM * NTOK], g_Vtl[(size_t)DIM * NTOK];  // [dim][token]
__device__ __nv_bfloat16 g_Ph[(size_t)NTOK * NTOK], g_Pl[(size_t)NTOK * NTOK];  // P~ = exp(score), unnormalized
__device__ float g_l[NTOK];   // row sums of P~

// ---------------------------------------------------------------------------
// helpers
// ---------------------------------------------------------------------------
__device__ __forceinline__ unsigned smem_u32(const void* p) {
    return (unsigned)__cvta_generic_to_shared(p);
}
__device__ __forceinline__ void cpa16(unsigned s, const void* g) {
    asm volatile("cp.async.cg.shared.global [%0],[%1],16;" :: "r"(s), "l"(g));
}
__device__ __forceinline__ void cpa_commit() {
    asm volatile("cp.async.commit_group;" ::: "memory");
}
__device__ __forceinline__ void cpa_wait0() {
    asm volatile("cp.async.wait_group 0;" ::: "memory");
}
__device__ __forceinline__ void cpa_wait1() {
    asm volatile("cp.async.wait_group 1;" ::: "memory");
}
__device__ __forceinline__ void ldsm4(unsigned r[4], unsigned addr) {
    asm volatile("ldmatrix.sync.aligned.m8n8.x4.shared.b16 {%0,%1,%2,%3},[%4];"
                 : "=r"(r[0]), "=r"(r[1]), "=r"(r[2]), "=r"(r[3]) : "r"(addr));
}
__device__ __forceinline__ void mma_bf16(float c[4], const unsigned a[4], const unsigned b[2]) {
    asm volatile("mma.sync.aligned.m16n8k16.row.col.f32.bf16.bf16.f32 "
                 "{%0,%1,%2,%3},{%4,%5,%6,%7},{%8,%9},{%0,%1,%2,%3};"
                 : "+f"(c[0]), "+f"(c[1]), "+f"(c[2]), "+f"(c[3])
                 : "r"(a[0]), "r"(a[1]), "r"(a[2]), "r"(a[3]), "r"(b[0]), "r"(b[1]));
}

// ---------------------------------------------------------------------------
// one 128x128xKT tile of split-MMA; warp tile 32x32 (16 warps)
// ---------------------------------------------------------------------------
__device__ __forceinline__ void mma_tile(const char* sb, int lane, int wm, int wn,
                                         float acc[2][4][4])
{
    const __nv_bfloat16 (*Ah)[BPADE] = (const __nv_bfloat16(*)[BPADE])(sb);
    const __nv_bfloat16 (*Al)[BPADE] = (const __nv_bfloat16(*)[BPADE])(sb + ARR_BYTES);
    const __nv_bfloat16 (*Bh)[BPADE] = (const __nv_bfloat16(*)[BPADE])(sb + 2 * ARR_BYTES);
    const __nv_bfloat16 (*Bl)[BPADE] = (const __nv_bfloat16(*)[BPADE])(sb + 3 * ARR_BYTES);

#pragma unroll
    for (int kk = 0; kk < KT; kk += 16) {
        unsigned ah[2][4], al[2][4], bh[2][4], bl[2][4];
        int arow = (lane & 7) + ((lane >> 3) & 1) * 8;
        int acol = kk + (lane >> 4) * 8;
#pragma unroll
        for (int mi = 0; mi < 2; mi++) {
            int r = wm * 32 + mi * 16 + arow;
            ldsm4(ah[mi], smem_u32(&Ah[r][acol]));
            ldsm4(al[mi], smem_u32(&Al[r][acol]));
        }
        int brow = (lane & 7) + ((lane >> 4) & 1) * 8;
        int bcol = kk + ((lane >> 3) & 1) * 8;
#pragma unroll
        for (int p = 0; p < 2; p++) {
            int n = wn * 32 + p * 16 + brow;
            ldsm4(bh[p], smem_u32(&Bh[n][bcol]));
            ldsm4(bl[p], smem_u32(&Bl[n][bcol]));
        }
#pragma unroll
        for (int mi = 0; mi < 2; mi++)
#pragma unroll
            for (int ni = 0; ni < 4; ni++) {
                const unsigned* bhp = &bh[ni >> 1][(ni & 1) * 2];
                const unsigned* blp = &bl[ni >> 1][(ni & 1) * 2];
                mma_bf16(acc[mi][ni], ah[mi], bhp);
                mma_bf16(acc[mi][ni], ah[mi], blp);
                mma_bf16(acc[mi][ni], al[mi], bhp);
            }
    }
}

// ---------------------------------------------------------------------------
// stage loader: 4 cp.async x 16B per thread (512 threads cover 128 rows x 4 arrays)
// ---------------------------------------------------------------------------
__device__ __forceinline__ void load_stage(
    unsigned st,
    const __nv_bfloat16* gAh, const __nv_bfloat16* gAl,
    const __nv_bfloat16* gBh, const __nv_bfloat16* gBl, int koff)
{
    cpa16(st, gAh + koff);
    cpa16(st + ARR_BYTES, gAl + koff);
    cpa16(st + 2 * ARR_BYTES, gBh + koff);
    cpa16(st + 3 * ARR_BYTES, gBl + koff);
}

// 3-stage pipelined mainloop. A rows at rowBase, B rows at colBase, k-contig.
template <int KITERS>
__device__ __forceinline__ void gemm_core(
    const __nv_bfloat16* __restrict__ Agh, const __nv_bfloat16* __restrict__ Agl, int sA,
    const __nv_bfloat16* __restrict__ Bgh, const __nv_bfloat16* __restrict__ Bgl, int sB,
    int rowBase, int colBase, char* smem, float acc[2][4][4])
{
    int tid = threadIdx.x;
    int row = tid >> 2, ck = (tid & 3) * 8;

    const __nv_bfloat16* gAh = Agh + (size_t)(rowBase + row) * sA + ck;
    const __nv_bfloat16* gAl = Agl + (size_t)(rowBase + row) * sA + ck;
    const __nv_bfloat16* gBh = Bgh + (size_t)(colBase + row) * sB + ck;
    const __nv_bfloat16* gBl = Bgl + (size_t)(colBase + row) * sB + ck;

    unsigned s0 = smem_u32(smem) + (row * BPADE + ck) * 2;
    int lane = tid & 31, warp = tid >> 5, wm = warp >> 2, wn = warp & 3;

    // prologue: stages 0 and 1
    load_stage(s0, gAh, gAl, gBh, gBl, 0);
    cpa_commit();
    load_stage(s0 + STAGE_BYTES, gAh, gAl, gBh, gBl, KT);
    cpa_commit();

    for (int it = 0; it < KITERS; it++) {
        if (it == KITERS - 1) cpa_wait0(); else cpa_wait1();
        __syncthreads();
        if (it + 2 < KITERS) {
            load_stage(s0 + ((it + 2) % NSTAGE) * STAGE_BYTES,
                       gAh, gAl, gBh, gBl, (it + 2) * KT);
            cpa_commit();
        }
        mma_tile(smem + (it % NSTAGE) * STAGE_BYTES, lane, wm, wn, acc);
    }
}

// ---------------------------------------------------------------------------
// elementwise fp32 -> bf16 hi/lo split
// ---------------------------------------------------------------------------
__global__ __launch_bounds__(256) void split_kernel(
    const float* __restrict__ src, __nv_bfloat16* __restrict__ h,
    __nv_bfloat16* __restrict__ l, int n)
{
    int i = (blockIdx.x * 256 + threadIdx.x) * 4;
    if (i >= n) return;
    float4 v = *(const float4*)(src + i);
    float f[4] = {v.x, v.y, v.z, v.w};
    __nv_bfloat16 hh[4], ll[4];
#pragma unroll
    for (int j = 0; j < 4; j++) {
        hh[j] = __float2bfloat16(f[j]);
        ll[j] = __float2bfloat16(f[j] - __bfloat162float(hh[j]));
    }
    ((__nv_bfloat162*)(h + i))[0] = __halves2bfloat162(hh[0], hh[1]);
    ((__nv_bfloat162*)(h + i))[1] = __halves2bfloat162(hh[2], hh[3]);
    ((__nv_bfloat162*)(l + i))[0] = __halves2bfloat162(ll[0], ll[1]);
    ((__nv_bfloat162*)(l + i))[1] = __halves2bfloat162(ll[2], ll[3]);
}

// zero row-sum accumulators (must run every launch: atomics accumulate)
__global__ __launch_bounds__(1024) void zero_l_kernel()
{
    g_l[blockIdx.x * 1024 + threadIdx.x] = 0.0f;
}

// ---------------------------------------------------------------------------
// QKV: out = x @ W^T + b, split-stored. z=2 (V) stored transposed [dim][token].
// grid (64, 8, 3), block 512
// ---------------------------------------------------------------------------
__global__ __launch_bounds__(NTHR, 1) void qkv_mma(
    const float* __restrict__ bq, const float* __restrict__ bk,
    const float* __restrict__ bv)
{
    extern __shared__ char smem[];
    int z = blockIdx.z;
    const float* bias = (z == 0) ? bq : (z == 1) ? bk : bv;

    int tid = threadIdx.x, lane = tid & 31, warp = tid >> 5;
    int wm = warp >> 2, wn = warp & 3;
    int rowBase = blockIdx.x * 128, colBase = blockIdx.y * 128;

    float acc[2][4][4] = {};
    gemm_core<DIM / KT>(g_xh, g_xl, DIM, g_Wh[z], g_Wl[z], DIM,
                        rowBase, colBase, smem, acc);

    if (z < 2) {
        __nv_bfloat16* oh = (z == 0) ? g_Qh : g_Kh;
        __nv_bfloat16* ol = (z == 0) ? g_Ql : g_Kl;
#pragma unroll
        for (int mi = 0; mi < 2; mi++)
#pragma unroll
            for (int ni = 0; ni < 4; ni++) {
                int r = rowBase + wm * 32 + mi * 16 + (lane >> 2);
                int c = colBase + wn * 32 + ni * 8 + (lane & 3) * 2;
                float b0 = bias[c], b1 = bias[c + 1];
#pragma unroll
                for (int hr = 0; hr < 2; hr++) {
                    float v0 = acc[mi][ni][hr * 2] + b0;
                    float v1 = acc[mi][ni][hr * 2 + 1] + b1;
                    __nv_bfloat16 h0 = __float2bfloat16(v0), h1 = __float2bfloat16(v1);
                    size_t o = (size_t)(r + hr * 8) * DIM + c;
                    *(__nv_bfloat162*)(oh + o) = __halves2bfloat162(h0, h1);
                    *(__nv_bfloat162*)(ol + o) = __halves2bfloat162(
                        __float2bfloat16(v0 - __bfloat162float(h0)),
                        __float2bfloat16(v1 - __bfloat162float(h1)));
                }
            }
    } else {
        // V: transpose via smem, store [dim][token]
        __syncthreads();  // done with mainloop buffers
        __nv_bfloat16 (*Th)[136] = (__nv_bfloat16(*)[136])(smem);
        __nv_bfloat16 (*Tl)[136] = (__nv_bfloat16(*)[136])(smem + 128 * 136 * 2);
#pragma unroll
        for (int mi = 0; mi < 2; mi++)
#pragma unroll
            for (int ni = 0; ni < 4; ni++) {
                int rL = wm * 32 + mi * 16 + (lane >> 2);
                int cL = wn * 32 + ni * 8 + (lane & 3) * 2;
                float b0 = bias[colBase + cL], b1 = bias[colBase + cL + 1];
#pragma unroll
                for (int hr = 0; hr < 2; hr++) {
                    float v0 = acc[mi][ni][hr * 2] + b0;
                    float v1 = acc[mi][ni][hr * 2 + 1] + b1;
                    __nv_bfloat16 h0 = __float2bfloat16(v0), h1 = __float2bfloat16(v1);
                    Th[cL][rL + hr * 8] = h0;
                    Th[cL + 1][rL + hr * 8] = h1;
                    Tl[cL][rL + hr * 8] = __float2bfloat16(v0 - __bfloat162float(h0));
                    Tl[cL + 1][rL + hr * 8] = __float2bfloat16(v1 - __bfloat162float(h1));
                }
            }
        __syncthreads();
#pragma unroll
        for (int j = 0; j < 4; j++) {
            int idx = j * NTHR + tid;
            int cRow = idx >> 4, ch = (idx & 15) * 8;
            float4 vh = *(float4*)&Th[cRow][ch];
            float4 vl = *(float4*)&Tl[cRow][ch];
            size_t o = (size_t)(colBase + cRow) * NTOK + rowBase + ch;
            *(float4*)(g_Vth + o) = vh;
            *(float4*)(g_Vtl + o) = vl;
        }
    }
}

// ---------------------------------------------------------------------------
// Scores fused with exp: P~ = exp((Q K^T)/32 - |dt|/86400), row sums -> g_l.
// No max subtraction: scores bounded (|QK/32| <~ 6, bias in [-10,0]) so exp
// is safe in fp32. softmax normalization folded into out_mma.
// grid (64, 64), block 512
// ---------------------------------------------------------------------------
__global__ __launch_bounds__(NTHR, 1) void scores_mma(const float* __restrict__ ts)
{
    extern __shared__ char smem[];
    int tid = threadIdx.x, lane = tid & 31, warp = tid >> 5;
    int wm = warp >> 2, wn = warp & 3;
    int rowBase = blockIdx.x * 128, colBase = blockIdx.y * 128;

    float acc[2][4][4] = {};
    gemm_core<DIM / KT>(g_Qh, g_Ql, DIM, g_Kh, g_Kl, DIM,
                        rowBase, colBase, smem, acc);

    const float inv_scale = 1.0f / 32.0f;
    const float inv_T = 1.0f / 86400.0f;

#pragma unroll
    for (int mi = 0; mi < 2; mi++) {
        int r = rowBase + wm * 32 + mi * 16 + (lane >> 2);
        float t_r0 = ts[r], t_r1 = ts[r + 8];
        float sum0 = 0.0f, sum1 = 0.0f;
#pragma unroll
        for (int ni = 0; ni < 4; ni++) {
            int c = colBase + wn * 32 + ni * 8 + (lane & 3) * 2;
            float tc0 = ts[c], tc1 = ts[c + 1];
            float p00 = __expf(acc[mi][ni][0] * inv_scale - fabsf(t_r0 - tc0) * inv_T);
            float p01 = __expf(acc[mi][ni][1] * inv_scale - fabsf(t_r0 - tc1) * inv_T);
            float p10 = __expf(acc[mi][ni][2] * inv_scale - fabsf(t_r1 - tc0) * inv_T);
            float p11 = __expf(acc[mi][ni][3] * inv_scale - fabsf(t_r1 - tc1) * inv_T);
            sum0 += p00 + p01;
            sum1 += p10 + p11;

            __nv_bfloat16 h00 = __float2bfloat16(p00), h01 = __float2bfloat16(p01);
            __nv_bfloat16 h10 = __float2bfloat16(p10), h11 = __float2bfloat16(p11);
            size_t o0 = (size_t)r * NTOK + c;
            size_t o1 = (size_t)(r + 8) * NTOK + c;
            *(__nv_bfloat162*)(g_Ph + o0) = __halves2bfloat162(h00, h01);
            *(__nv_bfloat162*)(g_Ph + o1) = __halves2bfloat162(h10, h11);
            *(__nv_bfloat162*)(g_Pl + o0) = __halves2bfloat162(
                __float2bfloat16(p00 - __bfloat162float(h00)),
                __float2bfloat16(p01 - __bfloat162float(h01)));
            *(__nv_bfloat162*)(g_Pl + o1) = __halves2bfloat162(
                __float2bfloat16(p10 - __bfloat162float(h10)),
                __float2bfloat16(p11 - __bfloat162float(h11)));
        }
        // quad-reduce (lanes l^1, l^2 share the same rows, hold different cols)
        sum0 += __shfl_xor_sync(0xffffffff, sum0, 1);
        sum0 += __shfl_xor_sync(0xffffffff, sum0, 2);
        sum1 += __shfl_xor_sync(0xffffffff, sum1, 1);
        sum1 += __shfl_xor_sync(0xffffffff, sum1, 2);
        if ((lane & 3) == 0) {
            atomicAdd(&g_l[r], sum0);
            atomicAdd(&g_l[r + 8], sum1);
        }
    }
}

// ---------------------------------------------------------------------------
// Output: O = diag(1/l) P~ @ V.  grid (64, 8), block 512
// ---------------------------------------------------------------------------
__global__ __launch_bounds__(NTHR, 1) void out_mma(float* __restrict__ O)
{
    extern __shared__ char smem[];
    int tid = threadIdx.x, lane = tid & 31, warp = tid >> 5;
    int wm = warp >> 2, wn = warp & 3;
    int rowBase = blockIdx.x * 128, colBase = blockIdx.y * 128;

    float acc[2][4][4] = {};
    gemm_core<NTOK / KT>(g_Ph, g_Pl, NTOK, g_Vth, g_Vtl, NTOK,
                         rowBase, colBase, smem, acc);

#pragma unroll
    for (int mi = 0; mi < 2; mi++) {
        int r = rowBase + wm * 32 + mi * 16 + (lane >> 2);
        float i0 = 1.0f / g_l[r], i1 = 1.0f / g_l[r + 8];
#pragma unroll
        for (int ni = 0; ni < 4; ni++) {
            int c = colBase + wn * 32 + ni * 8 + (lane & 3) * 2;
            *(float2*)(O + (size_t)r * DIM + c) =
                make_float2(acc[mi][ni][0] * i0, acc[mi][ni][1] * i0);
            *(float2*)(O + (size_t)(r + 8) * DIM + c) =
                make_float2(acc[mi][ni][2] * i1, acc[mi][ni][3] * i1);
        }
    }
}

// ---------------------------------------------------------------------------
extern "C" void kernel_launch(void* const* d_in, const int* in_sizes, int n_in,
                              void* d_out, int out_size)
{
    const float* x  = (const float*)d_in[0];
    const float* ts = (const float*)d_in[1];
    const float* Wq = (const float*)d_in[2];
    const float* bq = (const float*)d_in[3];
    const float* Wk = (const float*)d_in[4];
    const float* bk = (const float*)d_in[5];
    const float* Wv = (const float*)d_in[6];
    const float* bv = (const float*)d_in[7];
    float* out = (float*)d_out;

    cudaFuncSetAttribute(qkv_mma,    cudaFuncAttributeMaxDynamicSharedMemorySize, SMEM_TOTAL);
    cudaFuncSetAttribute(scores_mma, cudaFuncAttributeMaxDynamicSharedMemorySize, SMEM_TOTAL);
    cudaFuncSetAttribute(out_mma,    cudaFuncAttributeMaxDynamicSharedMemorySize, SMEM_TOTAL);

    __nv_bfloat16 *xh, *xl, *wh0, *wl0;
    cudaGetSymbolAddress((void**)&xh, g_xh);
    cudaGetSymbolAddress((void**)&xl, g_xl);
    cudaGetSymbolAddress((void**)&wh0, g_Wh);
    cudaGetSymbolAddress((void**)&wl0, g_Wl);

    const size_t ND = (size_t)NTOK * DIM, DD = (size_t)DIM * DIM;
    split_kernel<<<(int)(ND / 1024), 256>>>(x, xh, xl, (int)ND);
    split_kernel<<<(int)(DD / 1024), 256>>>(Wq, wh0,          wl0,          (int)DD);
    split_kernel<<<(int)(DD / 1024), 256>>>(Wk, wh0 + DD,     wl0 + DD,     (int)DD);
    split_kernel<<<(int)(DD / 1024), 256>>>(Wv, wh0 + 2 * DD, wl0 + 2 * DD, (int)DD);
    zero_l_kernel<<<NTOK / 1024, 1024>>>();

    qkv_mma<<<dim3(NTOK / 128, DIM / 128, 3), NTHR, SMEM_TOTAL>>>(bq, bk, bv);
    scores_mma<<<dim3(NTOK / 128, NTOK / 128), NTHR, SMEM_TOTAL>>>(ts);
    out_mma<<<dim3(NTOK / 128, DIM / 128), NTHR, SMEM_TOTAL>>>(out);
}

// round 8
// speedup vs baseline: 1.2686x; 1.2533x over previous
#include <cuda_runtime.h>
#include <cuda_fp16.h>
#include <math.h>

#define NTOK 8192
#define DIM  1024
#define KT   32          // k-tile depth (fp16 elements)
#define BPADE 40         // smem row stride in elements (80B = 5*16B)
#define ARR_BYTES 10240  // 128 * 40 * 2
#define NSTAGE 3
#define NTHR 512
#define SMEM_QKV (3 * 4 * ARR_BYTES)   // Ah,Al,Bh,Bl
#define SMEM_SO  (3 * 3 * ARR_BYTES)   // Ah,Al,Bh

// ---------------------------------------------------------------------------
// Scratch (static device globals)
// ---------------------------------------------------------------------------
__device__ __half g_xh[(size_t)NTOK * DIM], g_xl[(size_t)NTOK * DIM];
__device__ __half g_Wh[3][(size_t)DIM * DIM], g_Wl[3][(size_t)DIM * DIM];
__device__ __half g_Qh[(size_t)NTOK * DIM], g_Ql[(size_t)NTOK * DIM];
__device__ __half g_Kh[(size_t)NTOK * DIM];                       // single limb
__device__ __half g_Vth[(size_t)DIM * NTOK];                      // [dim][token], single limb
__device__ __half g_Ph[(size_t)NTOK * NTOK], g_Pl[(size_t)NTOK * NTOK];  // P~ = exp(score)
__device__ float g_l[NTOK];   // row sums of P~

// ---------------------------------------------------------------------------
// helpers
// ---------------------------------------------------------------------------
__device__ __forceinline__ unsigned smem_u32(const void* p) {
    return (unsigned)__cvta_generic_to_shared(p);
}
__device__ __forceinline__ void cpa16(unsigned s, const void* g) {
    asm volatile("cp.async.cg.shared.global [%0],[%1],16;" :: "r"(s), "l"(g));
}
__device__ __forceinline__ void cpa_commit() {
    asm volatile("cp.async.commit_group;" ::: "memory");
}
__device__ __forceinline__ void cpa_wait0() {
    asm volatile("cp.async.wait_group 0;" ::: "memory");
}
__device__ __forceinline__ void cpa_wait1() {
    asm volatile("cp.async.wait_group 1;" ::: "memory");
}
__device__ __forceinline__ void ldsm4(unsigned r[4], unsigned addr) {
    asm volatile("ldmatrix.sync.aligned.m8n8.x4.shared.b16 {%0,%1,%2,%3},[%4];"
                 : "=r"(r[0]), "=r"(r[1]), "=r"(r[2]), "=r"(r[3]) : "r"(addr));
}
__device__ __forceinline__ void mma_f16(float c[4], const unsigned a[4], const unsigned b[2]) {
    asm volatile("mma.sync.aligned.m16n8k16.row.col.f32.f16.f16.f32 "
                 "{%0,%1,%2,%3},{%4,%5,%6,%7},{%8,%9},{%0,%1,%2,%3};"
                 : "+f"(c[0]), "+f"(c[1]), "+f"(c[2]), "+f"(c[3])
                 : "r"(a[0]), "r"(a[1]), "r"(a[2]), "r"(a[3]), "r"(b[0]), "r"(b[1]));
}
__device__ __forceinline__ __half2 mkh2(__half a, __half b) { return __halves2half2(a, b); }

// ---------------------------------------------------------------------------
// one 128x128xKT tile; warp tile 32x32 (16 warps). BLO: B has lo limb (3 MMAs)
// ---------------------------------------------------------------------------
template <bool BLO>
__device__ __forceinline__ void mma_tile(const char* sb, int lane, int wm, int wn,
                                         float acc[2][4][4])
{
    const __half (*Ah)[BPADE] = (const __half(*)[BPADE])(sb);
    const __half (*Al)[BPADE] = (const __half(*)[BPADE])(sb + ARR_BYTES);
    const __half (*Bh)[BPADE] = (const __half(*)[BPADE])(sb + 2 * ARR_BYTES);
    const __half (*Bl)[BPADE] = (const __half(*)[BPADE])(sb + 3 * ARR_BYTES);

#pragma unroll
    for (int kk = 0; kk < KT; kk += 16) {
        unsigned ah[2][4], al[2][4], bh[2][4], bl[2][4];
        int arow = (lane & 7) + ((lane >> 3) & 1) * 8;
        int acol = kk + (lane >> 4) * 8;
#pragma unroll
        for (int mi = 0; mi < 2; mi++) {
            int r = wm * 32 + mi * 16 + arow;
            ldsm4(ah[mi], smem_u32(&Ah[r][acol]));
            ldsm4(al[mi], smem_u32(&Al[r][acol]));
        }
        int brow = (lane & 7) + ((lane >> 4) & 1) * 8;
        int bcol = kk + ((lane >> 3) & 1) * 8;
#pragma unroll
        for (int p = 0; p < 2; p++) {
            int n = wn * 32 + p * 16 + brow;
            ldsm4(bh[p], smem_u32(&Bh[n][bcol]));
            if (BLO) ldsm4(bl[p], smem_u32(&Bl[n][bcol]));
        }
#pragma unroll
        for (int mi = 0; mi < 2; mi++)
#pragma unroll
            for (int ni = 0; ni < 4; ni++) {
                const unsigned* bhp = &bh[ni >> 1][(ni & 1) * 2];
                mma_f16(acc[mi][ni], ah[mi], bhp);
                mma_f16(acc[mi][ni], al[mi], bhp);
                if (BLO) {
                    const unsigned* blp = &bl[ni >> 1][(ni & 1) * 2];
                    mma_f16(acc[mi][ni], ah[mi], blp);
                }
            }
    }
}

// ---------------------------------------------------------------------------
// 3-stage pipelined mainloop. A rows at rowBase, B rows at colBase, k-contig.
// ---------------------------------------------------------------------------
template <int KITERS, bool BLO>
__device__ __forceinline__ void gemm_core(
    const __half* __restrict__ Agh, const __half* __restrict__ Agl, int sA,
    const __half* __restrict__ Bgh, const __half* __restrict__ Bgl, int sB,
    int rowBase, int colBase, char* smem, float acc[2][4][4])
{
    constexpr int STAGE = (BLO ? 4 : 3) * ARR_BYTES;
    int tid = threadIdx.x;
    int row = tid >> 2, ck = (tid & 3) * 8;

    const __half* gAh = Agh + (size_t)(rowBase + row) * sA + ck;
    const __half* gAl = Agl + (size_t)(rowBase + row) * sA + ck;
    const __half* gBh = Bgh + (size_t)(colBase + row) * sB + ck;
    const __half* gBl = BLO ? (Bgl + (size_t)(colBase + row) * sB + ck) : nullptr;

    unsigned s0 = smem_u32(smem) + (row * BPADE + ck) * 2;
    int lane = tid & 31, warp = tid >> 5, wm = warp >> 2, wn = warp & 3;

#pragma unroll
    for (int pr = 0; pr < 2; pr++) {
        unsigned b = s0 + pr * STAGE;
        int koff = pr * KT;
        cpa16(b, gAh + koff);
        cpa16(b + ARR_BYTES, gAl + koff);
        cpa16(b + 2 * ARR_BYTES, gBh + koff);
        if (BLO) cpa16(b + 3 * ARR_BYTES, gBl + koff);
        cpa_commit();
    }

    for (int it = 0; it < KITERS; it++) {
        if (it == KITERS - 1) cpa_wait0(); else cpa_wait1();
        __syncthreads();
        if (it + 2 < KITERS) {
            unsigned b = s0 + ((it + 2) % NSTAGE) * STAGE;
            int koff = (it + 2) * KT;
            cpa16(b, gAh + koff);
            cpa16(b + ARR_BYTES, gAl + koff);
            cpa16(b + 2 * ARR_BYTES, gBh + koff);
            if (BLO) cpa16(b + 3 * ARR_BYTES, gBl + koff);
            cpa_commit();
        }
        mma_tile<BLO>(smem + (it % NSTAGE) * STAGE, lane, wm, wn, acc);
    }
}

// ---------------------------------------------------------------------------
// elementwise fp32 -> fp16 hi/lo split
// ---------------------------------------------------------------------------
__global__ __launch_bounds__(256) void split_kernel(
    const float* __restrict__ src, __half* __restrict__ h,
    __half* __restrict__ l, int n)
{
    int i = (blockIdx.x * 256 + threadIdx.x) * 4;
    if (i >= n) return;
    float4 v = *(const float4*)(src + i);
    float f[4] = {v.x, v.y, v.z, v.w};
    __half hh[4], ll[4];
#pragma unroll
    for (int j = 0; j < 4; j++) {
        hh[j] = __float2half_rn(f[j]);
        ll[j] = __float2half_rn(f[j] - __half2float(hh[j]));
    }
    ((__half2*)(h + i))[0] = mkh2(hh[0], hh[1]);
    ((__half2*)(h + i))[1] = mkh2(hh[2], hh[3]);
    ((__half2*)(l + i))[0] = mkh2(ll[0], ll[1]);
    ((__half2*)(l + i))[1] = mkh2(ll[2], ll[3]);
}

// zero row-sum accumulators (must run every launch: atomics accumulate)
__global__ __launch_bounds__(1024) void zero_l_kernel()
{
    g_l[blockIdx.x * 1024 + threadIdx.x] = 0.0f;
}

// ---------------------------------------------------------------------------
// QKV: out = x @ W^T + b. z=0: Q (2 limbs); z=1: K (1 limb); z=2: V transposed (1 limb)
// grid (64, 8, 3), block 512
// ---------------------------------------------------------------------------
__global__ __launch_bounds__(NTHR, 1) void qkv_mma(
    const float* __restrict__ bq, const float* __restrict__ bk,
    const float* __restrict__ bv)
{
    extern __shared__ char smem[];
    int z = blockIdx.z;
    const float* bias = (z == 0) ? bq : (z == 1) ? bk : bv;

    int tid = threadIdx.x, lane = tid & 31, warp = tid >> 5;
    int wm = warp >> 2, wn = warp & 3;
    int rowBase = blockIdx.x * 128, colBase = blockIdx.y * 128;

    float acc[2][4][4] = {};
    gemm_core<DIM / KT, true>(g_xh, g_xl, DIM, g_Wh[z], g_Wl[z], DIM,
                              rowBase, colBase, smem, acc);

    if (z == 0) {
#pragma unroll
        for (int mi = 0; mi < 2; mi++)
#pragma unroll
            for (int ni = 0; ni < 4; ni++) {
                int r = rowBase + wm * 32 + mi * 16 + (lane >> 2);
                int c = colBase + wn * 32 + ni * 8 + (lane & 3) * 2;
                float b0 = bias[c], b1 = bias[c + 1];
#pragma unroll
                for (int hr = 0; hr < 2; hr++) {
                    float v0 = acc[mi][ni][hr * 2] + b0;
                    float v1 = acc[mi][ni][hr * 2 + 1] + b1;
                    __half h0 = __float2half_rn(v0), h1 = __float2half_rn(v1);
                    size_t o = (size_t)(r + hr * 8) * DIM + c;
                    *(__half2*)(g_Qh + o) = mkh2(h0, h1);
                    *(__half2*)(g_Ql + o) = mkh2(
                        __float2half_rn(v0 - __half2float(h0)),
                        __float2half_rn(v1 - __half2float(h1)));
                }
            }
    } else if (z == 1) {
#pragma unroll
        for (int mi = 0; mi < 2; mi++)
#pragma unroll
            for (int ni = 0; ni < 4; ni++) {
                int r = rowBase + wm * 32 + mi * 16 + (lane >> 2);
                int c = colBase + wn * 32 + ni * 8 + (lane & 3) * 2;
                float b0 = bias[c], b1 = bias[c + 1];
#pragma unroll
                for (int hr = 0; hr < 2; hr++) {
                    float v0 = acc[mi][ni][hr * 2] + b0;
                    float v1 = acc[mi][ni][hr * 2 + 1] + b1;
                    size_t o = (size_t)(r + hr * 8) * DIM + c;
                    *(__half2*)(g_Kh + o) = mkh2(__float2half_rn(v0), __float2half_rn(v1));
                }
            }
    } else {
        // V: transpose via smem, store [dim][token], single limb
        __syncthreads();  // done with mainloop buffers
        __half (*Th)[136] = (__half(*)[136])(smem);
#pragma unroll
        for (int mi = 0; mi < 2; mi++)
#pragma unroll
            for (int ni = 0; ni < 4; ni++) {
                int rL = wm * 32 + mi * 16 + (lane >> 2);
                int cL = wn * 32 + ni * 8 + (lane & 3) * 2;
                float b0 = bias[colBase + cL], b1 = bias[colBase + cL + 1];
#pragma unroll
                for (int hr = 0; hr < 2; hr++) {
                    Th[cL][rL + hr * 8]     = __float2half_rn(acc[mi][ni][hr * 2] + b0);
                    Th[cL + 1][rL + hr * 8] = __float2half_rn(acc[mi][ni][hr * 2 + 1] + b1);
                }
            }
        __syncthreads();
#pragma unroll
        for (int j = 0; j < 4; j++) {
            int idx = j * NTHR + tid;
            int cRow = idx >> 4, ch = (idx & 15) * 8;
            float4 vh = *(float4*)&Th[cRow][ch];
            *(float4*)(g_Vth + (size_t)(colBase + cRow) * NTOK + rowBase + ch) = vh;
        }
    }
}

// ---------------------------------------------------------------------------
// Scores fused with exp: P~ = exp((Q K^T)/32 - |dt|/86400), row sums -> g_l.
// Q 2-limb x K 1-limb (2 MMAs). grid (64, 64), block 512
// ---------------------------------------------------------------------------
__global__ __launch_bounds__(NTHR, 1) void scores_mma(const float* __restrict__ ts)
{
    extern __shared__ char smem[];
    int tid = threadIdx.x, lane = tid & 31, warp = tid >> 5;
    int wm = warp >> 2, wn = warp & 3;
    int rowBase = blockIdx.x * 128, colBase = blockIdx.y * 128;

    float acc[2][4][4] = {};
    gemm_core<DIM / KT, false>(g_Qh, g_Ql, DIM, g_Kh, nullptr, DIM,
                               rowBase, colBase, smem, acc);

    const float inv_scale = 1.0f / 32.0f;
    const float inv_T = 1.0f / 86400.0f;

#pragma unroll
    for (int mi = 0; mi < 2; mi++) {
        int r = rowBase + wm * 32 + mi * 16 + (lane >> 2);
        float t_r0 = ts[r], t_r1 = ts[r + 8];
        float sum0 = 0.0f, sum1 = 0.0f;
#pragma unroll
        for (int ni = 0; ni < 4; ni++) {
            int c = colBase + wn * 32 + ni * 8 + (lane & 3) * 2;
            float tc0 = ts[c], tc1 = ts[c + 1];
            float p00 = __expf(acc[mi][ni][0] * inv_scale - fabsf(t_r0 - tc0) * inv_T);
            float p01 = __expf(acc[mi][ni][1] * inv_scale - fabsf(t_r0 - tc1) * inv_T);
            float p10 = __expf(acc[mi][ni][2] * inv_scale - fabsf(t_r1 - tc0) * inv_T);
            float p11 = __expf(acc[mi][ni][3] * inv_scale - fabsf(t_r1 - tc1) * inv_T);
            sum0 += p00 + p01;
            sum1 += p10 + p11;

            __half h00 = __float2half_rn(p00), h01 = __float2half_rn(p01);
            __half h10 = __float2half_rn(p10), h11 = __float2half_rn(p11);
            size_t o0 = (size_t)r * NTOK + c;
            size_t o1 = (size_t)(r + 8) * NTOK + c;
            *(__half2*)(g_Ph + o0) = mkh2(h00, h01);
            *(__half2*)(g_Ph + o1) = mkh2(h10, h11);
            *(__half2*)(g_Pl + o0) = mkh2(
                __float2half_rn(p00 - __half2float(h00)),
                __float2half_rn(p01 - __half2float(h01)));
            *(__half2*)(g_Pl + o1) = mkh2(
                __float2half_rn(p10 - __half2float(h10)),
                __float2half_rn(p11 - __half2float(h11)));
        }
        sum0 += __shfl_xor_sync(0xffffffff, sum0, 1);
        sum0 += __shfl_xor_sync(0xffffffff, sum0, 2);
        sum1 += __shfl_xor_sync(0xffffffff, sum1, 1);
        sum1 += __shfl_xor_sync(0xffffffff, sum1, 2);
        if ((lane & 3) == 0) {
            atomicAdd(&g_l[r], sum0);
            atomicAdd(&g_l[r + 8], sum1);
        }
    }
}

// ---------------------------------------------------------------------------
// Output: O = diag(1/l) P~ @ V.  P 2-limb x Vt 1-limb (2 MMAs). grid (64, 8)
// ---------------------------------------------------------------------------
__global__ __launch_bounds__(NTHR, 1) void out_mma(float* __restrict__ O)
{
    extern __shared__ char smem[];
    int tid = threadIdx.x, lane = tid & 31, warp = tid >> 5;
    int wm = warp >> 2, wn = warp & 3;
    int rowBase = blockIdx.x * 128, colBase = blockIdx.y * 128;

    float acc[2][4][4] = {};
    gemm_core<NTOK / KT, false>(g_Ph, g_Pl, NTOK, g_Vth, nullptr, NTOK,
                                rowBase, colBase, smem, acc);

#pragma unroll
    for (int mi = 0; mi < 2; mi++) {
        int r = rowBase + wm * 32 + mi * 16 + (lane >> 2);
        float i0 = 1.0f / g_l[r], i1 = 1.0f / g_l[r + 8];
#pragma unroll
        for (int ni = 0; ni < 4; ni++) {
            int c = colBase + wn * 32 + ni * 8 + (lane & 3) * 2;
            *(float2*)(O + (size_t)r * DIM + c) =
                make_float2(acc[mi][ni][0] * i0, acc[mi][ni][1] * i0);
            *(float2*)(O + (size_t)(r + 8) * DIM + c) =
                make_float2(acc[mi][ni][2] * i1, acc[mi][ni][3] * i1);
        }
    }
}

// ---------------------------------------------------------------------------
extern "C" void kernel_launch(void* const* d_in, const int* in_sizes, int n_in,
                              void* d_out, int out_size)
{
    const float* x  = (const float*)d_in[0];
    const float* ts = (const float*)d_in[1];
    const float* Wq = (const float*)d_in[2];
    const float* bq = (const float*)d_in[3];
    const float* Wk = (const float*)d_in[4];
    const float* bk = (const float*)d_in[5];
    const float* Wv = (const float*)d_in[6];
    const float* bv = (const float*)d_in[7];
    float* out = (float*)d_out;

    cudaFuncSetAttribute(qkv_mma,    cudaFuncAttributeMaxDynamicSharedMemorySize, SMEM_QKV);
    cudaFuncSetAttribute(scores_mma, cudaFuncAttributeMaxDynamicSharedMemorySize, SMEM_SO);
    cudaFuncSetAttribute(out_mma,    cudaFuncAttributeMaxDynamicSharedMemorySize, SMEM_SO);

    __half *xh, *xl, *wh0, *wl0;
    cudaGetSymbolAddress((void**)&xh, g_xh);
    cudaGetSymbolAddress((void**)&xl, g_xl);
    cudaGetSymbolAddress((void**)&wh0, g_Wh);
    cudaGetSymbolAddress((void**)&wl0, g_Wl);

    const size_t ND = (size_t)NTOK * DIM, DD = (size_t)DIM * DIM;
    split_kernel<<<(int)(ND / 1024), 256>>>(x, xh, xl, (int)ND);
    split_kernel<<<(int)(DD / 1024), 256>>>(Wq, wh0,          wl0,          (int)DD);
    split_kernel<<<(int)(DD / 1024), 256>>>(Wk, wh0 + DD,     wl0 + DD,     (int)DD);
    split_kernel<<<(int)(DD / 1024), 256>>>(Wv, wh0 + 2 * DD, wl0 + 2 * DD, (int)DD);
    zero_l_kernel<<<NTOK / 1024, 1024>>>();

    qkv_mma<<<dim3(NTOK / 128, DIM / 128, 3), NTHR, SMEM_QKV>>>(bq, bk, bv);
    scores_mma<<<dim3(NTOK / 128, NTOK / 128), NTHR, SMEM_SO>>>(ts);
    out_mma<<<dim3(NTOK / 128, DIM / 128), NTHR, SMEM_SO>>>(out);
}

// round 9
// speedup vs baseline: 2.0580x; 1.6222x over previous
#include <cuda_runtime.h>
#include <cuda_fp16.h>
#include <math.h>

#define NTOK 8192
#define DIM  1024
#define KT   32          // k-tile depth (fp16 elements)
#define BPADE 40         // smem row stride in elements (80B = 5*16B)
#define ARR_BYTES 10240  // 128 * 40 * 2
#define NSTAGE 3
#define NTHR 512
#define SMEM_QKV (3 * 4 * ARR_BYTES)   // Ah,Al,Bh,Bl
#define SMEM_SO  (3 * 2 * ARR_BYTES)   // Ah,Bh

// ---------------------------------------------------------------------------
// Scratch (static device globals)
// ---------------------------------------------------------------------------
__device__ __half g_xh[(size_t)NTOK * DIM], g_xl[(size_t)NTOK * DIM];
__device__ __half g_Wh[3][(size_t)DIM * DIM], g_Wl[3][(size_t)DIM * DIM];
__device__ __half g_Qh[(size_t)NTOK * DIM];                       // single limb
__device__ __half g_Kh[(size_t)NTOK * DIM];                       // single limb
__device__ __half g_Vth[(size_t)DIM * NTOK];                      // [dim][token], single limb
__device__ __half g_Ph[(size_t)NTOK * NTOK];                      // P~ = exp(score), single limb
__device__ float g_l[NTOK];   // row sums of P~

// ---------------------------------------------------------------------------
// helpers
// ---------------------------------------------------------------------------
__device__ __forceinline__ unsigned smem_u32(const void* p) {
    return (unsigned)__cvta_generic_to_shared(p);
}
__device__ __forceinline__ void cpa16(unsigned s, const void* g) {
    asm volatile("cp.async.cg.shared.global [%0],[%1],16;" :: "r"(s), "l"(g));
}
__device__ __forceinline__ void cpa_commit() {
    asm volatile("cp.async.commit_group;" ::: "memory");
}
__device__ __forceinline__ void cpa_wait0() {
    asm volatile("cp.async.wait_group 0;" ::: "memory");
}
__device__ __forceinline__ void cpa_wait1() {
    asm volatile("cp.async.wait_group 1;" ::: "memory");
}
__device__ __forceinline__ void ldsm4(unsigned r[4], unsigned addr) {
    asm volatile("ldmatrix.sync.aligned.m8n8.x4.shared.b16 {%0,%1,%2,%3},[%4];"
                 : "=r"(r[0]), "=r"(r[1]), "=r"(r[2]), "=r"(r[3]) : "r"(addr));
}
__device__ __forceinline__ void mma_f16(float c[4], const unsigned a[4], const unsigned b[2]) {
    asm volatile("mma.sync.aligned.m16n8k16.row.col.f32.f16.f16.f32 "
                 "{%0,%1,%2,%3},{%4,%5,%6,%7},{%8,%9},{%0,%1,%2,%3};"
                 : "+f"(c[0]), "+f"(c[1]), "+f"(c[2]), "+f"(c[3])
                 : "r"(a[0]), "r"(a[1]), "r"(a[2]), "r"(a[3]), "r"(b[0]), "r"(b[1]));
}
__device__ __forceinline__ __half2 mkh2(__half a, __half b) { return __halves2half2(a, b); }

// ---------------------------------------------------------------------------
// one 128x128xKT tile; warp tile 32x32 (16 warps).
// FULL: 3-MMA hi/lo split (4 smem arrays); else single MMA (2 arrays)
// ---------------------------------------------------------------------------
template <bool FULL>
__device__ __forceinline__ void mma_tile(const char* sb, int lane, int wm, int wn,
                                         float acc[2][4][4])
{
    const __half (*Ah)[BPADE] = (const __half(*)[BPADE])(sb);
    const __half (*Al)[BPADE] = (const __half(*)[BPADE])(sb + ARR_BYTES);
    const __half (*Bh)[BPADE] = (const __half(*)[BPADE])(sb + (FULL ? 2 : 1) * ARR_BYTES);
    const __half (*Bl)[BPADE] = (const __half(*)[BPADE])(sb + 3 * ARR_BYTES);

#pragma unroll
    for (int kk = 0; kk < KT; kk += 16) {
        unsigned ah[2][4], al[2][4], bh[2][4], bl[2][4];
        int arow = (lane & 7) + ((lane >> 3) & 1) * 8;
        int acol = kk + (lane >> 4) * 8;
#pragma unroll
        for (int mi = 0; mi < 2; mi++) {
            int r = wm * 32 + mi * 16 + arow;
            ldsm4(ah[mi], smem_u32(&Ah[r][acol]));
            if (FULL) ldsm4(al[mi], smem_u32(&Al[r][acol]));
        }
        int brow = (lane & 7) + ((lane >> 4) & 1) * 8;
        int bcol = kk + ((lane >> 3) & 1) * 8;
#pragma unroll
        for (int p = 0; p < 2; p++) {
            int n = wn * 32 + p * 16 + brow;
            ldsm4(bh[p], smem_u32(&Bh[n][bcol]));
            if (FULL) ldsm4(bl[p], smem_u32(&Bl[n][bcol]));
        }
#pragma unroll
        for (int mi = 0; mi < 2; mi++)
#pragma unroll
            for (int ni = 0; ni < 4; ni++) {
                const unsigned* bhp = &bh[ni >> 1][(ni & 1) * 2];
                mma_f16(acc[mi][ni], ah[mi], bhp);
                if (FULL) {
                    const unsigned* blp = &bl[ni >> 1][(ni & 1) * 2];
                    mma_f16(acc[mi][ni], al[mi], bhp);
                    mma_f16(acc[mi][ni], ah[mi], blp);
                }
            }
    }
}

// ---------------------------------------------------------------------------
// 3-stage pipelined mainloop. A rows at rowBase, B rows at colBase, k-contig.
// ---------------------------------------------------------------------------
template <int KITERS, bool FULL>
__device__ __forceinline__ void gemm_core(
    const __half* __restrict__ Agh, const __half* __restrict__ Agl, int sA,
    const __half* __restrict__ Bgh, const __half* __restrict__ Bgl, int sB,
    int rowBase, int colBase, char* smem, float acc[2][4][4])
{
    constexpr int STAGE = (FULL ? 4 : 2) * ARR_BYTES;
    int tid = threadIdx.x;
    int row = tid >> 2, ck = (tid & 3) * 8;

    const __half* gAh = Agh + (size_t)(rowBase + row) * sA + ck;
    const __half* gAl = FULL ? (Agl + (size_t)(rowBase + row) * sA + ck) : nullptr;
    const __half* gBh = Bgh + (size_t)(colBase + row) * sB + ck;
    const __half* gBl = FULL ? (Bgl + (size_t)(colBase + row) * sB + ck) : nullptr;

    unsigned s0 = smem_u32(smem) + (row * BPADE + ck) * 2;
    int lane = tid & 31, warp = tid >> 5, wm = warp >> 2, wn = warp & 3;

#pragma unroll
    for (int pr = 0; pr < 2; pr++) {
        unsigned b = s0 + pr * STAGE;
        int koff = pr * KT;
        cpa16(b, gAh + koff);
        if (FULL) cpa16(b + ARR_BYTES, gAl + koff);
        cpa16(b + (FULL ? 2 : 1) * ARR_BYTES, gBh + koff);
        if (FULL) cpa16(b + 3 * ARR_BYTES, gBl + koff);
        cpa_commit();
    }

    for (int it = 0; it < KITERS; it++) {
        if (it == KITERS - 1) cpa_wait0(); else cpa_wait1();
        __syncthreads();
        if (it + 2 < KITERS) {
            unsigned b = s0 + ((it + 2) % NSTAGE) * STAGE;
            int koff = (it + 2) * KT;
            cpa16(b, gAh + koff);
            if (FULL) cpa16(b + ARR_BYTES, gAl + koff);
            cpa16(b + (FULL ? 2 : 1) * ARR_BYTES, gBh + koff);
            if (FULL) cpa16(b + 3 * ARR_BYTES, gBl + koff);
            cpa_commit();
        }
        mma_tile<FULL>(smem + (it % NSTAGE) * STAGE, lane, wm, wn, acc);
    }
}

// ---------------------------------------------------------------------------
// elementwise fp32 -> fp16 hi/lo split
// ---------------------------------------------------------------------------
__global__ __launch_bounds__(256) void split_kernel(
    const float* __restrict__ src, __half* __restrict__ h,
    __half* __restrict__ l, int n)
{
    int i = (blockIdx.x * 256 + threadIdx.x) * 4;
    if (i >= n) return;
    float4 v = *(const float4*)(src + i);
    float f[4] = {v.x, v.y, v.z, v.w};
    __half hh[4], ll[4];
#pragma unroll
    for (int j = 0; j < 4; j++) {
        hh[j] = __float2half_rn(f[j]);
        ll[j] = __float2half_rn(f[j] - __half2float(hh[j]));
    }
    ((__half2*)(h + i))[0] = mkh2(hh[0], hh[1]);
    ((__half2*)(h + i))[1] = mkh2(hh[2], hh[3]);
    ((__half2*)(l + i))[0] = mkh2(ll[0], ll[1]);
    ((__half2*)(l + i))[1] = mkh2(ll[2], ll[3]);
}

// zero row-sum accumulators (must run every launch: atomics accumulate)
__global__ __launch_bounds__(1024) void zero_l_kernel()
{
    g_l[blockIdx.x * 1024 + threadIdx.x] = 0.0f;
}

// ---------------------------------------------------------------------------
// QKV: out = x @ W^T + b (3-MMA split for accuracy).
// z=0: Q; z=1: K; z=2: V transposed. All stored single fp16 limb.
// grid (64, 8, 3), block 512
// ---------------------------------------------------------------------------
__global__ __launch_bounds__(NTHR, 1) void qkv_mma(
    const float* __restrict__ bq, const float* __restrict__ bk,
    const float* __restrict__ bv)
{
    extern __shared__ char smem[];
    int z = blockIdx.z;
    const float* bias = (z == 0) ? bq : (z == 1) ? bk : bv;

    int tid = threadIdx.x, lane = tid & 31, warp = tid >> 5;
    int wm = warp >> 2, wn = warp & 3;
    int rowBase = blockIdx.x * 128, colBase = blockIdx.y * 128;

    float acc[2][4][4] = {};
    gemm_core<DIM / KT, true>(g_xh, g_xl, DIM, g_Wh[z], g_Wl[z], DIM,
                              rowBase, colBase, smem, acc);

    if (z < 2) {
        __half* oh = (z == 0) ? g_Qh : g_Kh;
#pragma unroll
        for (int mi = 0; mi < 2; mi++)
#pragma unroll
            for (int ni = 0; ni < 4; ni++) {
                int r = rowBase + wm * 32 + mi * 16 + (lane >> 2);
                int c = colBase + wn * 32 + ni * 8 + (lane & 3) * 2;
                float b0 = bias[c], b1 = bias[c + 1];
#pragma unroll
                for (int hr = 0; hr < 2; hr++) {
                    float v0 = acc[mi][ni][hr * 2] + b0;
                    float v1 = acc[mi][ni][hr * 2 + 1] + b1;
                    size_t o = (size_t)(r + hr * 8) * DIM + c;
                    *(__half2*)(oh + o) = mkh2(__float2half_rn(v0), __float2half_rn(v1));
                }
            }
    } else {
        // V: transpose via smem, store [dim][token], single limb
        __syncthreads();  // done with mainloop buffers
        __half (*Th)[136] = (__half(*)[136])(smem);
#pragma unroll
        for (int mi = 0; mi < 2; mi++)
#pragma unroll
            for (int ni = 0; ni < 4; ni++) {
                int rL = wm * 32 + mi * 16 + (lane >> 2);
                int cL = wn * 32 + ni * 8 + (lane & 3) * 2;
                float b0 = bias[colBase + cL], b1 = bias[colBase + cL + 1];
#pragma unroll
                for (int hr = 0; hr < 2; hr++) {
                    Th[cL][rL + hr * 8]     = __float2half_rn(acc[mi][ni][hr * 2] + b0);
                    Th[cL + 1][rL + hr * 8] = __float2half_rn(acc[mi][ni][hr * 2 + 1] + b1);
                }
            }
        __syncthreads();
#pragma unroll
        for (int j = 0; j < 4; j++) {
            int idx = j * NTHR + tid;
            int cRow = idx >> 4, ch = (idx & 15) * 8;
            float4 vh = *(float4*)&Th[cRow][ch];
            *(float4*)(g_Vth + (size_t)(colBase + cRow) * NTOK + rowBase + ch) = vh;
        }
    }
}

// ---------------------------------------------------------------------------
// Scores fused with exp: P~ = exp((Q K^T)/32 - |dt|/86400), row sums -> g_l.
// Single-limb Q x K (1 MMA). grid (64, 64), block 512
// ---------------------------------------------------------------------------
__global__ __launch_bounds__(NTHR, 1) void scores_mma(const float* __restrict__ ts)
{
    extern __shared__ char smem[];
    int tid = threadIdx.x, lane = tid & 31, warp = tid >> 5;
    int wm = warp >> 2, wn = warp & 3;
    int rowBase = blockIdx.x * 128, colBase = blockIdx.y * 128;

    float acc[2][4][4] = {};
    gemm_core<DIM / KT, false>(g_Qh, nullptr, DIM, g_Kh, nullptr, DIM,
                               rowBase, colBase, smem, acc);

    const float inv_scale = 1.0f / 32.0f;
    const float inv_T = 1.0f / 86400.0f;

#pragma unroll
    for (int mi = 0; mi < 2; mi++) {
        int r = rowBase + wm * 32 + mi * 16 + (lane >> 2);
        float t_r0 = ts[r], t_r1 = ts[r + 8];
        float sum0 = 0.0f, sum1 = 0.0f;
#pragma unroll
        for (int ni = 0; ni < 4; ni++) {
            int c = colBase + wn * 32 + ni * 8 + (lane & 3) * 2;
            float tc0 = ts[c], tc1 = ts[c + 1];
            float p00 = __expf(acc[mi][ni][0] * inv_scale - fabsf(t_r0 - tc0) * inv_T);
            float p01 = __expf(acc[mi][ni][1] * inv_scale - fabsf(t_r0 - tc1) * inv_T);
            float p10 = __expf(acc[mi][ni][2] * inv_scale - fabsf(t_r1 - tc0) * inv_T);
            float p11 = __expf(acc[mi][ni][3] * inv_scale - fabsf(t_r1 - tc1) * inv_T);
            sum0 += p00 + p01;
            sum1 += p10 + p11;
            *(__half2*)(g_Ph + (size_t)r * NTOK + c) =
                mkh2(__float2half_rn(p00), __float2half_rn(p01));
            *(__half2*)(g_Ph + (size_t)(r + 8) * NTOK + c) =
                mkh2(__float2half_rn(p10), __float2half_rn(p11));
        }
        sum0 += __shfl_xor_sync(0xffffffff, sum0, 1);
        sum0 += __shfl_xor_sync(0xffffffff, sum0, 2);
        sum1 += __shfl_xor_sync(0xffffffff, sum1, 1);
        sum1 += __shfl_xor_sync(0xffffffff, sum1, 2);
        if ((lane & 3) == 0) {
            atomicAdd(&g_l[r], sum0);
            atomicAdd(&g_l[r + 8], sum1);
        }
    }
}

// ---------------------------------------------------------------------------
// Output: O = diag(1/l) P~ @ V. Single-limb P x Vt (1 MMA). grid (64, 8)
// ---------------------------------------------------------------------------
__global__ __launch_bounds__(NTHR, 1) void out_mma(float* __restrict__ O)
{
    extern __shared__ char smem[];
    int tid = threadIdx.x, lane = tid & 31, warp = tid >> 5;
    int wm = warp >> 2, wn = warp & 3;
    int rowBase = blockIdx.x * 128, colBase = blockIdx.y * 128;

    float acc[2][4][4] = {};
    gemm_core<NTOK / KT, false>(g_Ph, nullptr, NTOK, g_Vth, nullptr, NTOK,
                                rowBase, colBase, smem, acc);

#pragma unroll
    for (int mi = 0; mi < 2; mi++) {
        int r = rowBase + wm * 32 + mi * 16 + (lane >> 2);
        float i0 = 1.0f / g_l[r], i1 = 1.0f / g_l[r + 8];
#pragma unroll
        for (int ni = 0; ni < 4; ni++) {
            int c = colBase + wn * 32 + ni * 8 + (lane & 3) * 2;
            *(float2*)(O + (size_t)r * DIM + c) =
                make_float2(acc[mi][ni][0] * i0, acc[mi][ni][1] * i0);
            *(float2*)(O + (size_t)(r + 8) * DIM + c) =
                make_float2(acc[mi][ni][2] * i1, acc[mi][ni][3] * i1);
        }
    }
}

// ---------------------------------------------------------------------------
extern "C" void kernel_launch(void* const* d_in, const int* in_sizes, int n_in,
                              void* d_out, int out_size)
{
    const float* x  = (const float*)d_in[0];
    const float* ts = (const float*)d_in[1];
    const float* Wq = (const float*)d_in[2];
    const float* bq = (const float*)d_in[3];
    const float* Wk = (const float*)d_in[4];
    const float* bk = (const float*)d_in[5];
    const float* Wv = (const float*)d_in[6];
    const float* bv = (const float*)d_in[7];
    float* out = (float*)d_out;

    cudaFuncSetAttribute(qkv_mma,    cudaFuncAttributeMaxDynamicSharedMemorySize, SMEM_QKV);
    cudaFuncSetAttribute(scores_mma, cudaFuncAttributeMaxDynamicSharedMemorySize, SMEM_SO);
    cudaFuncSetAttribute(out_mma,    cudaFuncAttributeMaxDynamicSharedMemorySize, SMEM_SO);

    __half *xh, *xl, *wh0, *wl0;
    cudaGetSymbolAddress((void**)&xh, g_xh);
    cudaGetSymbolAddress((void**)&xl, g_xl);
    cudaGetSymbolAddress((void**)&wh0, g_Wh);
    cudaGetSymbolAddress((void**)&wl0, g_Wl);

    const size_t ND = (size_t)NTOK * DIM, DD = (size_t)DIM * DIM;
    split_kernel<<<(int)(ND / 1024), 256>>>(x, xh, xl, (int)ND);
    split_kernel<<<(int)(DD / 1024), 256>>>(Wq, wh0,          wl0,          (int)DD);
    split_kernel<<<(int)(DD / 1024), 256>>>(Wk, wh0 + DD,     wl0 + DD,     (int)DD);
    split_kernel<<<(int)(DD / 1024), 256>>>(Wv, wh0 + 2 * DD, wl0 + 2 * DD, (int)DD);
    zero_l_kernel<<<NTOK / 1024, 1024>>>();

    qkv_mma<<<dim3(NTOK / 128, DIM / 128, 3), NTHR, SMEM_QKV>>>(bq, bk, bv);
    scores_mma<<<dim3(NTOK / 128, NTOK / 128), NTHR, SMEM_SO>>>(ts);
    out_mma<<<dim3(NTOK / 128, DIM / 128), NTHR, SMEM_SO>>>(out);
}

// round 10
// speedup vs baseline: 2.2278x; 1.0825x over previous
#include <cuda_runtime.h>
#include <cuda_fp16.h>
#include <math.h>

#define NTOK 8192
#define DIM  1024
#define KT   32          // k-tile depth (fp16 elements)
#define BPADE 40         // smem row stride in elements (80B = 5*16B)
#define ARR_BYTES 10240  // 128 * 40 * 2
#define NSTAGE 3
#define NTHR 512
#define SMEM_QKV (3 * 3 * ARR_BYTES)   // Ah,Al,Bh
#define SMEM_SO  (3 * 2 * ARR_BYTES)   // Ah,Bh

// ---------------------------------------------------------------------------
// Scratch (static device globals)
// ---------------------------------------------------------------------------
__device__ __half g_xh[(size_t)NTOK * DIM], g_xl[(size_t)NTOK * DIM];
__device__ __half g_Wh[3][(size_t)DIM * DIM];
__device__ __half g_Qh[(size_t)NTOK * DIM];                       // single limb
__device__ __half g_Kh[(size_t)NTOK * DIM];                       // single limb
__device__ __half g_Vth[(size_t)DIM * NTOK];                      // [dim][token], single limb
__device__ __half g_Ph[(size_t)NTOK * NTOK];                      // P~ = exp(score), single limb
__device__ float g_l[NTOK];   // row sums of P~

// ---------------------------------------------------------------------------
// helpers
// ---------------------------------------------------------------------------
__device__ __forceinline__ unsigned smem_u32(const void* p) {
    return (unsigned)__cvta_generic_to_shared(p);
}
__device__ __forceinline__ void cpa16(unsigned s, const void* g) {
    asm volatile("cp.async.cg.shared.global [%0],[%1],16;" :: "r"(s), "l"(g));
}
__device__ __forceinline__ void cpa_commit() {
    asm volatile("cp.async.commit_group;" ::: "memory");
}
__device__ __forceinline__ void cpa_wait0() {
    asm volatile("cp.async.wait_group 0;" ::: "memory");
}
__device__ __forceinline__ void cpa_wait1() {
    asm volatile("cp.async.wait_group 1;" ::: "memory");
}
__device__ __forceinline__ void ldsm4(unsigned r[4], unsigned addr) {
    asm volatile("ldmatrix.sync.aligned.m8n8.x4.shared.b16 {%0,%1,%2,%3},[%4];"
                 : "=r"(r[0]), "=r"(r[1]), "=r"(r[2]), "=r"(r[3]) : "r"(addr));
}
__device__ __forceinline__ void mma_f16(float c[4], const unsigned a[4], const unsigned b[2]) {
    asm volatile("mma.sync.aligned.m16n8k16.row.col.f32.f16.f16.f32 "
                 "{%0,%1,%2,%3},{%4,%5,%6,%7},{%8,%9},{%0,%1,%2,%3};"
                 : "+f"(c[0]), "+f"(c[1]), "+f"(c[2]), "+f"(c[3])
                 : "r"(a[0]), "r"(a[1]), "r"(a[2]), "r"(a[3]), "r"(b[0]), "r"(b[1]));
}
__device__ __forceinline__ __half2 mkh2(__half a, __half b) { return __halves2half2(a, b); }

// ---------------------------------------------------------------------------
// one 128x128xKT tile; warp tile 32x32 (16 warps).
// LIMBS==2: A hi/lo x B hi (2 MMAs, 3 arrays); LIMBS==1: single (2 arrays)
// ---------------------------------------------------------------------------
template <int LIMBS>
__device__ __forceinline__ void mma_tile(const char* sb, int lane, int wm, int wn,
                                         float acc[2][4][4])
{
    const __half (*Ah)[BPADE] = (const __half(*)[BPADE])(sb);
    const __half (*Al)[BPADE] = (const __half(*)[BPADE])(sb + ARR_BYTES);
    const __half (*Bh)[BPADE] = (const __half(*)[BPADE])(sb + (LIMBS == 2 ? 2 : 1) * ARR_BYTES);

#pragma unroll
    for (int kk = 0; kk < KT; kk += 16) {
        unsigned ah[2][4], al[2][4], bh[2][4];
        int arow = (lane & 7) + ((lane >> 3) & 1) * 8;
        int acol = kk + (lane >> 4) * 8;
#pragma unroll
        for (int mi = 0; mi < 2; mi++) {
            int r = wm * 32 + mi * 16 + arow;
            ldsm4(ah[mi], smem_u32(&Ah[r][acol]));
            if (LIMBS == 2) ldsm4(al[mi], smem_u32(&Al[r][acol]));
        }
        int brow = (lane & 7) + ((lane >> 4) & 1) * 8;
        int bcol = kk + ((lane >> 3) & 1) * 8;
#pragma unroll
        for (int p = 0; p < 2; p++) {
            int n = wn * 32 + p * 16 + brow;
            ldsm4(bh[p], smem_u32(&Bh[n][bcol]));
        }
#pragma unroll
        for (int mi = 0; mi < 2; mi++)
#pragma unroll
            for (int ni = 0; ni < 4; ni++) {
                const unsigned* bhp = &bh[ni >> 1][(ni & 1) * 2];
                mma_f16(acc[mi][ni], ah[mi], bhp);
                if (LIMBS == 2) mma_f16(acc[mi][ni], al[mi], bhp);
            }
    }
}

// ---------------------------------------------------------------------------
// 3-stage pipelined mainloop. A rows at rowBase, B rows at colBase, k-contig.
// ---------------------------------------------------------------------------
template <int KITERS, int LIMBS>
__device__ __forceinline__ void gemm_core(
    const __half* __restrict__ Agh, const __half* __restrict__ Agl, int sA,
    const __half* __restrict__ Bgh, int sB,
    int rowBase, int colBase, char* smem, float acc[2][4][4])
{
    constexpr int STAGE = (LIMBS == 2 ? 3 : 2) * ARR_BYTES;
    int tid = threadIdx.x;
    int row = tid >> 2, ck = (tid & 3) * 8;

    const __half* gAh = Agh + (size_t)(rowBase + row) * sA + ck;
    const __half* gAl = (LIMBS == 2) ? (Agl + (size_t)(rowBase + row) * sA + ck) : nullptr;
    const __half* gBh = Bgh + (size_t)(colBase + row) * sB + ck;

    unsigned s0 = smem_u32(smem) + (row * BPADE + ck) * 2;
    int lane = tid & 31, warp = tid >> 5, wm = warp >> 2, wn = warp & 3;

#pragma unroll
    for (int pr = 0; pr < 2; pr++) {
        unsigned b = s0 + pr * STAGE;
        int koff = pr * KT;
        cpa16(b, gAh + koff);
        if (LIMBS == 2) cpa16(b + ARR_BYTES, gAl + koff);
        cpa16(b + (LIMBS == 2 ? 2 : 1) * ARR_BYTES, gBh + koff);
        cpa_commit();
    }

    for (int it = 0; it < KITERS; it++) {
        if (it == KITERS - 1) cpa_wait0(); else cpa_wait1();
        __syncthreads();
        if (it + 2 < KITERS) {
            unsigned b = s0 + ((it + 2) % NSTAGE) * STAGE;
            int koff = (it + 2) * KT;
            cpa16(b, gAh + koff);
            if (LIMBS == 2) cpa16(b + ARR_BYTES, gAl + koff);
            cpa16(b + (LIMBS == 2 ? 2 : 1) * ARR_BYTES, gBh + koff);
            cpa_commit();
        }
        mma_tile<LIMBS>(smem + (it % NSTAGE) * STAGE, lane, wm, wn, acc);
    }
}

// ---------------------------------------------------------------------------
// fp32 -> fp16 hi/lo split (x) and hi-only (W)
// ---------------------------------------------------------------------------
__global__ __launch_bounds__(256) void split_kernel(
    const float* __restrict__ src, __half* __restrict__ h,
    __half* __restrict__ l, int n)
{
    int i = (blockIdx.x * 256 + threadIdx.x) * 4;
    if (i >= n) return;
    float4 v = *(const float4*)(src + i);
    float f[4] = {v.x, v.y, v.z, v.w};
    __half hh[4], ll[4];
#pragma unroll
    for (int j = 0; j < 4; j++) {
        hh[j] = __float2half_rn(f[j]);
        ll[j] = __float2half_rn(f[j] - __half2float(hh[j]));
    }
    ((__half2*)(h + i))[0] = mkh2(hh[0], hh[1]);
    ((__half2*)(h + i))[1] = mkh2(hh[2], hh[3]);
    ((__half2*)(l + i))[0] = mkh2(ll[0], ll[1]);
    ((__half2*)(l + i))[1] = mkh2(ll[2], ll[3]);
}

__global__ __launch_bounds__(256) void cvt_kernel(
    const float* __restrict__ src, __half* __restrict__ h, int n)
{
    int i = (blockIdx.x * 256 + threadIdx.x) * 4;
    if (i >= n) return;
    float4 v = *(const float4*)(src + i);
    ((__half2*)(h + i))[0] = __floats2half2_rn(v.x, v.y);
    ((__half2*)(h + i))[1] = __floats2half2_rn(v.z, v.w);
}

// zero row-sum accumulators (must run every launch: atomics accumulate)
__global__ __launch_bounds__(1024) void zero_l_kernel()
{
    g_l[blockIdx.x * 1024 + threadIdx.x] = 0.0f;
}

// ---------------------------------------------------------------------------
// QKV: out = x @ W^T + b (2-MMA: x hi/lo x W hi).
// z=0: Q; z=1: K; z=2: V transposed. All stored single fp16 limb.
// grid (64, 8, 3), block 512
// ---------------------------------------------------------------------------
__global__ __launch_bounds__(NTHR, 1) void qkv_mma(
    const float* __restrict__ bq, const float* __restrict__ bk,
    const float* __restrict__ bv)
{
    extern __shared__ char smem[];
    int z = blockIdx.z;
    const float* bias = (z == 0) ? bq : (z == 1) ? bk : bv;

    int tid = threadIdx.x, lane = tid & 31, warp = tid >> 5;
    int wm = warp >> 2, wn = warp & 3;
    int rowBase = blockIdx.x * 128, colBase = blockIdx.y * 128;

    float acc[2][4][4] = {};
    gemm_core<DIM / KT, 2>(g_xh, g_xl, DIM, g_Wh[z], DIM,
                           rowBase, colBase, smem, acc);

    if (z < 2) {
        __half* oh = (z == 0) ? g_Qh : g_Kh;
#pragma unroll
        for (int mi = 0; mi < 2; mi++)
#pragma unroll
            for (int ni = 0; ni < 4; ni++) {
                int r = rowBase + wm * 32 + mi * 16 + (lane >> 2);
                int c = colBase + wn * 32 + ni * 8 + (lane & 3) * 2;
                float b0 = bias[c], b1 = bias[c + 1];
#pragma unroll
                for (int hr = 0; hr < 2; hr++) {
                    size_t o = (size_t)(r + hr * 8) * DIM + c;
                    *(__half2*)(oh + o) = __floats2half2_rn(
                        acc[mi][ni][hr * 2] + b0, acc[mi][ni][hr * 2 + 1] + b1);
                }
            }
    } else {
        // V: transpose via smem, store [dim][token], single limb
        __syncthreads();  // done with mainloop buffers
        __half (*Th)[136] = (__half(*)[136])(smem);
#pragma unroll
        for (int mi = 0; mi < 2; mi++)
#pragma unroll
            for (int ni = 0; ni < 4; ni++) {
                int rL = wm * 32 + mi * 16 + (lane >> 2);
                int cL = wn * 32 + ni * 8 + (lane & 3) * 2;
                float b0 = bias[colBase + cL], b1 = bias[colBase + cL + 1];
#pragma unroll
                for (int hr = 0; hr < 2; hr++) {
                    Th[cL][rL + hr * 8]     = __float2half_rn(acc[mi][ni][hr * 2] + b0);
                    Th[cL + 1][rL + hr * 8] = __float2half_rn(acc[mi][ni][hr * 2 + 1] + b1);
                }
            }
        __syncthreads();
#pragma unroll
        for (int j = 0; j < 4; j++) {
            int idx = j * NTHR + tid;
            int cRow = idx >> 4, ch = (idx & 15) * 8;
            float4 vh = *(float4*)&Th[cRow][ch];
            *(float4*)(g_Vth + (size_t)(colBase + cRow) * NTOK + rowBase + ch) = vh;
        }
    }
}

// ---------------------------------------------------------------------------
// Scores fused with exp: P~ = exp((Q K^T)/32 - |dt|/86400), row sums -> g_l.
// Single-limb Q x K (1 MMA). grid (64, 64), block 512
// ---------------------------------------------------------------------------
__global__ __launch_bounds__(NTHR, 1) void scores_mma(const float* __restrict__ ts)
{
    extern __shared__ char smem[];
    int tid = threadIdx.x, lane = tid & 31, warp = tid >> 5;
    int wm = warp >> 2, wn = warp & 3;
    int rowBase = blockIdx.x * 128, colBase = blockIdx.y * 128;

    float acc[2][4][4] = {};
    gemm_core<DIM / KT, 1>(g_Qh, nullptr, DIM, g_Kh, DIM,
                           rowBase, colBase, smem, acc);

    const float inv_scale = 1.0f / 32.0f;
    const float inv_T = 1.0f / 86400.0f;

#pragma unroll
    for (int mi = 0; mi < 2; mi++) {
        int r = rowBase + wm * 32 + mi * 16 + (lane >> 2);
        float t_r0 = ts[r], t_r1 = ts[r + 8];
        float sum0 = 0.0f, sum1 = 0.0f;
#pragma unroll
        for (int ni = 0; ni < 4; ni++) {
            int c = colBase + wn * 32 + ni * 8 + (lane & 3) * 2;
            float tc0 = ts[c], tc1 = ts[c + 1];
            float p00 = __expf(acc[mi][ni][0] * inv_scale - fabsf(t_r0 - tc0) * inv_T);
            float p01 = __expf(acc[mi][ni][1] * inv_scale - fabsf(t_r0 - tc1) * inv_T);
            float p10 = __expf(acc[mi][ni][2] * inv_scale - fabsf(t_r1 - tc0) * inv_T);
            float p11 = __expf(acc[mi][ni][3] * inv_scale - fabsf(t_r1 - tc1) * inv_T);
            sum0 += p00 + p01;
            sum1 += p10 + p11;
            *(__half2*)(g_Ph + (size_t)r * NTOK + c) = __floats2half2_rn(p00, p01);
            *(__half2*)(g_Ph + (size_t)(r + 8) * NTOK + c) = __floats2half2_rn(p10, p11);
        }
        sum0 += __shfl_xor_sync(0xffffffff, sum0, 1);
        sum0 += __shfl_xor_sync(0xffffffff, sum0, 2);
        sum1 += __shfl_xor_sync(0xffffffff, sum1, 1);
        sum1 += __shfl_xor_sync(0xffffffff, sum1, 2);
        if ((lane & 3) == 0) {
            atomicAdd(&g_l[r], sum0);
            atomicAdd(&g_l[r + 8], sum1);
        }
    }
}

// ---------------------------------------------------------------------------
// Output: O = diag(1/l) P~ @ V. Single-limb P x Vt (1 MMA). grid (64, 8)
// ---------------------------------------------------------------------------
__global__ __launch_bounds__(NTHR, 1) void out_mma(float* __restrict__ O)
{
    extern __shared__ char smem[];
    int tid = threadIdx.x, lane = tid & 31, warp = tid >> 5;
    int wm = warp >> 2, wn = warp & 3;
    int rowBase = blockIdx.x * 128, colBase = blockIdx.y * 128;

    float acc[2][4][4] = {};
    gemm_core<NTOK / KT, 1>(g_Ph, nullptr, NTOK, g_Vth, NTOK,
                            rowBase, colBase, smem, acc);

#pragma unroll
    for (int mi = 0; mi < 2; mi++) {
        int r = rowBase + wm * 32 + mi * 16 + (lane >> 2);
        float i0 = 1.0f / g_l[r], i1 = 1.0f / g_l[r + 8];
#pragma unroll
        for (int ni = 0; ni < 4; ni++) {
            int c = colBase + wn * 32 + ni * 8 + (lane & 3) * 2;
            *(float2*)(O + (size_t)r * DIM + c) =
                make_float2(acc[mi][ni][0] * i0, acc[mi][ni][1] * i0);
            *(float2*)(O + (size_t)(r + 8) * DIM + c) =
                make_float2(acc[mi][ni][2] * i1, acc[mi][ni][3] * i1);
        }
    }
}

// ---------------------------------------------------------------------------
extern "C" void kernel_launch(void* const* d_in, const int* in_sizes, int n_in,
                              void* d_out, int out_size)
{
    const float* x  = (const float*)d_in[0];
    const float* ts = (const float*)d_in[1];
    const float* Wq = (const float*)d_in[2];
    const float* bq = (const float*)d_in[3];
    const float* Wk = (const float*)d_in[4];
    const float* bk = (const float*)d_in[5];
    const float* Wv = (const float*)d_in[6];
    const float* bv = (const float*)d_in[7];
    float* out = (float*)d_out;

    cudaFuncSetAttribute(qkv_mma,    cudaFuncAttributeMaxDynamicSharedMemorySize, SMEM_QKV);
    cudaFuncSetAttribute(scores_mma, cudaFuncAttributeMaxDynamicSharedMemorySize, SMEM_SO);
    cudaFuncSetAttribute(out_mma,    cudaFuncAttributeMaxDynamicSharedMemorySize, SMEM_SO);

    __half *xh, *xl, *wh0;
    cudaGetSymbolAddress((void**)&xh, g_xh);
    cudaGetSymbolAddress((void**)&xl, g_xl);
    cudaGetSymbolAddress((void**)&wh0, g_Wh);

    const size_t ND = (size_t)NTOK * DIM, DD = (size_t)DIM * DIM;
    split_kernel<<<(int)(ND / 1024), 256>>>(x, xh, xl, (int)ND);
    cvt_kernel<<<(int)(DD / 1024), 256>>>(Wq, wh0,          (int)DD);
    cvt_kernel<<<(int)(DD / 1024), 256>>>(Wk, wh0 + DD,     (int)DD);
    cvt_kernel<<<(int)(DD / 1024), 256>>>(Wv, wh0 + 2 * DD, (int)DD);
    zero_l_kernel<<<NTOK / 1024, 1024>>>();

    qkv_mma<<<dim3(NTOK / 128, DIM / 128, 3), NTHR, SMEM_QKV>>>(bq, bk, bv);
    scores_mma<<<dim3(NTOK / 128, NTOK / 128), NTHR, SMEM_SO>>>(ts);
    out_mma<<<dim3(NTOK / 128, DIM / 128), NTHR, SMEM_SO>>>(out);
}

// round 11
// speedup vs baseline: 2.5877x; 1.1615x over previous
#include <cuda_runtime.h>
#include <cuda_fp16.h>
#include <math.h>

#define NTOK 8192
#define DIM  1024
#define KT   32          // k-tile depth (fp16 elements)
#define BPADE 40         // smem row stride in elements (80B = 5*16B)
#define ARR_BYTES 10240  // 128 * 40 * 2
#define NSTAGE 3
#define NTHR 512
#define SMEM_GEMM (3 * 2 * ARR_BYTES)   // A,B per stage, 3 stages

// ---------------------------------------------------------------------------
// Scratch (static device globals) — all operands single fp16 limb
// ---------------------------------------------------------------------------
__device__ __half g_xh[(size_t)NTOK * DIM];
__device__ __half g_Wh[3][(size_t)DIM * DIM];
__device__ __half g_Qh[(size_t)NTOK * DIM];
__device__ __half g_Kh[(size_t)NTOK * DIM];
__device__ __half g_Vth[(size_t)DIM * NTOK];                      // [dim][token]
__device__ __half g_Ph[(size_t)NTOK * NTOK];                      // P~ = exp(score)
__device__ float g_l[NTOK];   // row sums of P~

// ---------------------------------------------------------------------------
// helpers
// ---------------------------------------------------------------------------
__device__ __forceinline__ unsigned smem_u32(const void* p) {
    return (unsigned)__cvta_generic_to_shared(p);
}
__device__ __forceinline__ void cpa16(unsigned s, const void* g) {
    asm volatile("cp.async.cg.shared.global [%0],[%1],16;" :: "r"(s), "l"(g));
}
__device__ __forceinline__ void cpa_commit() {
    asm volatile("cp.async.commit_group;" ::: "memory");
}
__device__ __forceinline__ void cpa_wait0() {
    asm volatile("cp.async.wait_group 0;" ::: "memory");
}
__device__ __forceinline__ void cpa_wait1() {
    asm volatile("cp.async.wait_group 1;" ::: "memory");
}
__device__ __forceinline__ void ldsm4(unsigned r[4], unsigned addr) {
    asm volatile("ldmatrix.sync.aligned.m8n8.x4.shared.b16 {%0,%1,%2,%3},[%4];"
                 : "=r"(r[0]), "=r"(r[1]), "=r"(r[2]), "=r"(r[3]) : "r"(addr));
}
__device__ __forceinline__ void mma_f16(float c[4], const unsigned a[4], const unsigned b[2]) {
    asm volatile("mma.sync.aligned.m16n8k16.row.col.f32.f16.f16.f32 "
                 "{%0,%1,%2,%3},{%4,%5,%6,%7},{%8,%9},{%0,%1,%2,%3};"
                 : "+f"(c[0]), "+f"(c[1]), "+f"(c[2]), "+f"(c[3])
                 : "r"(a[0]), "r"(a[1]), "r"(a[2]), "r"(a[3]), "r"(b[0]), "r"(b[1]));
}

// ---------------------------------------------------------------------------
// one 128x128xKT tile; warp tile 32x32 (16 warps); single-limb (1 MMA/term)
// ---------------------------------------------------------------------------
__device__ __forceinline__ void mma_tile(const char* sb, int lane, int wm, int wn,
                                         float acc[2][4][4])
{
    const __half (*Ah)[BPADE] = (const __half(*)[BPADE])(sb);
    const __half (*Bh)[BPADE] = (const __half(*)[BPADE])(sb + ARR_BYTES);

#pragma unroll
    for (int kk = 0; kk < KT; kk += 16) {
        unsigned ah[2][4], bh[2][4];
        int arow = (lane & 7) + ((lane >> 3) & 1) * 8;
        int acol = kk + (lane >> 4) * 8;
#pragma unroll
        for (int mi = 0; mi < 2; mi++) {
            int r = wm * 32 + mi * 16 + arow;
            ldsm4(ah[mi], smem_u32(&Ah[r][acol]));
        }
        int brow = (lane & 7) + ((lane >> 4) & 1) * 8;
        int bcol = kk + ((lane >> 3) & 1) * 8;
#pragma unroll
        for (int p = 0; p < 2; p++) {
            int n = wn * 32 + p * 16 + brow;
            ldsm4(bh[p], smem_u32(&Bh[n][bcol]));
        }
#pragma unroll
        for (int mi = 0; mi < 2; mi++)
#pragma unroll
            for (int ni = 0; ni < 4; ni++)
                mma_f16(acc[mi][ni], ah[mi], &bh[ni >> 1][(ni & 1) * 2]);
    }
}

// ---------------------------------------------------------------------------
// 3-stage pipelined mainloop. A rows at rowBase, B rows at colBase, k-contig.
// ---------------------------------------------------------------------------
template <int KITERS>
__device__ __forceinline__ void gemm_core(
    const __half* __restrict__ Agh, int sA,
    const __half* __restrict__ Bgh, int sB,
    int rowBase, int colBase, char* smem, float acc[2][4][4])
{
    constexpr int STAGE = 2 * ARR_BYTES;
    int tid = threadIdx.x;
    int row = tid >> 2, ck = (tid & 3) * 8;

    const __half* gAh = Agh + (size_t)(rowBase + row) * sA + ck;
    const __half* gBh = Bgh + (size_t)(colBase + row) * sB + ck;

    unsigned s0 = smem_u32(smem) + (row * BPADE + ck) * 2;
    int lane = tid & 31, warp = tid >> 5, wm = warp >> 2, wn = warp & 3;

#pragma unroll
    for (int pr = 0; pr < 2; pr++) {
        unsigned b = s0 + pr * STAGE;
        cpa16(b, gAh + pr * KT);
        cpa16(b + ARR_BYTES, gBh + pr * KT);
        cpa_commit();
    }

    for (int it = 0; it < KITERS; it++) {
        if (it == KITERS - 1) cpa_wait0(); else cpa_wait1();
        __syncthreads();
        if (it + 2 < KITERS) {
            unsigned b = s0 + ((it + 2) % NSTAGE) * STAGE;
            cpa16(b, gAh + (it + 2) * KT);
            cpa16(b + ARR_BYTES, gBh + (it + 2) * KT);
            cpa_commit();
        }
        mma_tile(smem + (it % NSTAGE) * STAGE, lane, wm, wn, acc);
    }
}

// ---------------------------------------------------------------------------
// fp32 -> fp16 converts
// ---------------------------------------------------------------------------
__global__ __launch_bounds__(256) void cvt_x_kernel(const float* __restrict__ src)
{
    int i = (blockIdx.x * 256 + threadIdx.x) * 4;
    float4 v = *(const float4*)(src + i);
    ((__half2*)(g_xh + i))[0] = __floats2half2_rn(v.x, v.y);
    ((__half2*)(g_xh + i))[1] = __floats2half2_rn(v.z, v.w);
}

__global__ __launch_bounds__(256) void cvt_w_kernel(
    const float* __restrict__ Wq, const float* __restrict__ Wk,
    const float* __restrict__ Wv)
{
    int z = blockIdx.y;
    const float* src = (z == 0) ? Wq : (z == 1) ? Wk : Wv;
    __half* dst = g_Wh[z];
    int i = (blockIdx.x * 256 + threadIdx.x) * 4;
    float4 v = *(const float4*)(src + i);
    ((__half2*)(dst + i))[0] = __floats2half2_rn(v.x, v.y);
    ((__half2*)(dst + i))[1] = __floats2half2_rn(v.z, v.w);
}

// zero row-sum accumulators (must run every launch: atomics accumulate)
__global__ __launch_bounds__(1024) void zero_l_kernel()
{
    g_l[blockIdx.x * 1024 + threadIdx.x] = 0.0f;
}

// ---------------------------------------------------------------------------
// QKV: out = x @ W^T + b (1 MMA).  z=0: Q; z=1: K; z=2: V transposed.
// grid (64, 8, 3), block 512
// ---------------------------------------------------------------------------
__global__ __launch_bounds__(NTHR, 1) void qkv_mma(
    const float* __restrict__ bq, const float* __restrict__ bk,
    const float* __restrict__ bv)
{
    extern __shared__ char smem[];
    int z = blockIdx.z;
    const float* bias = (z == 0) ? bq : (z == 1) ? bk : bv;

    int tid = threadIdx.x, lane = tid & 31, warp = tid >> 5;
    int wm = warp >> 2, wn = warp & 3;
    int rowBase = blockIdx.x * 128, colBase = blockIdx.y * 128;

    float acc[2][4][4] = {};
    gemm_core<DIM / KT>(g_xh, DIM, g_Wh[z], DIM, rowBase, colBase, smem, acc);

    if (z < 2) {
        __half* oh = (z == 0) ? g_Qh : g_Kh;
#pragma unroll
        for (int mi = 0; mi < 2; mi++)
#pragma unroll
            for (int ni = 0; ni < 4; ni++) {
                int r = rowBase + wm * 32 + mi * 16 + (lane >> 2);
                int c = colBase + wn * 32 + ni * 8 + (lane & 3) * 2;
                float b0 = bias[c], b1 = bias[c + 1];
#pragma unroll
                for (int hr = 0; hr < 2; hr++) {
                    size_t o = (size_t)(r + hr * 8) * DIM + c;
                    *(__half2*)(oh + o) = __floats2half2_rn(
                        acc[mi][ni][hr * 2] + b0, acc[mi][ni][hr * 2 + 1] + b1);
                }
            }
    } else {
        // V: transpose via smem, store [dim][token]
        __syncthreads();  // done with mainloop buffers
        __half (*Th)[136] = (__half(*)[136])(smem);
#pragma unroll
        for (int mi = 0; mi < 2; mi++)
#pragma unroll
            for (int ni = 0; ni < 4; ni++) {
                int rL = wm * 32 + mi * 16 + (lane >> 2);
                int cL = wn * 32 + ni * 8 + (lane & 3) * 2;
                float b0 = bias[colBase + cL], b1 = bias[colBase + cL + 1];
#pragma unroll
                for (int hr = 0; hr < 2; hr++) {
                    Th[cL][rL + hr * 8]     = __float2half_rn(acc[mi][ni][hr * 2] + b0);
                    Th[cL + 1][rL + hr * 8] = __float2half_rn(acc[mi][ni][hr * 2 + 1] + b1);
                }
            }
        __syncthreads();
#pragma unroll
        for (int j = 0; j < 4; j++) {
            int idx = j * NTHR + tid;
            int cRow = idx >> 4, ch = (idx & 15) * 8;
            float4 vh = *(float4*)&Th[cRow][ch];
            *(float4*)(g_Vth + (size_t)(colBase + cRow) * NTOK + rowBase + ch) = vh;
        }
    }
}

// ---------------------------------------------------------------------------
// Scores fused with exp: P~ = exp((Q K^T)/32 - |dt|/86400), row sums -> g_l.
// grid (64, 64), block 512
// ---------------------------------------------------------------------------
__global__ __launch_bounds__(NTHR, 1) void scores_mma(const float* __restrict__ ts)
{
    extern __shared__ char smem[];
    int tid = threadIdx.x, lane = tid & 31, warp = tid >> 5;
    int wm = warp >> 2, wn = warp & 3;
    int rowBase = blockIdx.x * 128, colBase = blockIdx.y * 128;

    float acc[2][4][4] = {};
    gemm_core<DIM / KT>(g_Qh, DIM, g_Kh, DIM, rowBase, colBase, smem, acc);

    const float inv_scale = 1.0f / 32.0f;
    const float inv_T = 1.0f / 86400.0f;

#pragma unroll
    for (int mi = 0; mi < 2; mi++) {
        int r = rowBase + wm * 32 + mi * 16 + (lane >> 2);
        float t_r0 = ts[r], t_r1 = ts[r + 8];
        float sum0 = 0.0f, sum1 = 0.0f;
#pragma unroll
        for (int ni = 0; ni < 4; ni++) {
            int c = colBase + wn * 32 + ni * 8 + (lane & 3) * 2;
            float tc0 = ts[c], tc1 = ts[c + 1];
            float p00 = __expf(acc[mi][ni][0] * inv_scale - fabsf(t_r0 - tc0) * inv_T);
            float p01 = __expf(acc[mi][ni][1] * inv_scale - fabsf(t_r0 - tc1) * inv_T);
            float p10 = __expf(acc[mi][ni][2] * inv_scale - fabsf(t_r1 - tc0) * inv_T);
            float p11 = __expf(acc[mi][ni][3] * inv_scale - fabsf(t_r1 - tc1) * inv_T);
            sum0 += p00 + p01;
            sum1 += p10 + p11;
            *(__half2*)(g_Ph + (size_t)r * NTOK + c) = __floats2half2_rn(p00, p01);
            *(__half2*)(g_Ph + (size_t)(r + 8) * NTOK + c) = __floats2half2_rn(p10, p11);
        }
        sum0 += __shfl_xor_sync(0xffffffff, sum0, 1);
        sum0 += __shfl_xor_sync(0xffffffff, sum0, 2);
        sum1 += __shfl_xor_sync(0xffffffff, sum1, 1);
        sum1 += __shfl_xor_sync(0xffffffff, sum1, 2);
        if ((lane & 3) == 0) {
            atomicAdd(&g_l[r], sum0);
            atomicAdd(&g_l[r + 8], sum1);
        }
    }
}

// ---------------------------------------------------------------------------
// Output: O = diag(1/l) P~ @ V.  grid (64, 8), block 512
// ---------------------------------------------------------------------------
__global__ __launch_bounds__(NTHR, 1) void out_mma(float* __restrict__ O)
{
    extern __shared__ char smem[];
    int tid = threadIdx.x, lane = tid & 31, warp = tid >> 5;
    int wm = warp >> 2, wn = warp & 3;
    int rowBase = blockIdx.x * 128, colBase = blockIdx.y * 128;

    float acc[2][4][4] = {};
    gemm_core<NTOK / KT>(g_Ph, NTOK, g_Vth, NTOK, rowBase, colBase, smem, acc);

#pragma unroll
    for (int mi = 0; mi < 2; mi++) {
        int r = rowBase + wm * 32 + mi * 16 + (lane >> 2);
        float i0 = 1.0f / g_l[r], i1 = 1.0f / g_l[r + 8];
#pragma unroll
        for (int ni = 0; ni < 4; ni++) {
            int c = colBase + wn * 32 + ni * 8 + (lane & 3) * 2;
            *(float2*)(O + (size_t)r * DIM + c) =
                make_float2(acc[mi][ni][0] * i0, acc[mi][ni][1] * i0);
            *(float2*)(O + (size_t)(r + 8) * DIM + c) =
                make_float2(acc[mi][ni][2] * i1, acc[mi][ni][3] * i1);
        }
    }
}

// ---------------------------------------------------------------------------
extern "C" void kernel_launch(void* const* d_in, const int* in_sizes, int n_in,
                              void* d_out, int out_size)
{
    const float* x  = (const float*)d_in[0];
    const float* ts = (const float*)d_in[1];
    const float* Wq = (const float*)d_in[2];
    const float* bq = (const float*)d_in[3];
    const float* Wk = (const float*)d_in[4];
    const float* bk = (const float*)d_in[5];
    const float* Wv = (const float*)d_in[6];
    const float* bv = (const float*)d_in[7];
    float* out = (float*)d_out;

    cudaFuncSetAttribute(qkv_mma,    cudaFuncAttributeMaxDynamicSharedMemorySize, SMEM_GEMM);
    cudaFuncSetAttribute(scores_mma, cudaFuncAttributeMaxDynamicSharedMemorySize, SMEM_GEMM);
    cudaFuncSetAttribute(out_mma,    cudaFuncAttributeMaxDynamicSharedMemorySize, SMEM_GEMM);

    const size_t ND = (size_t)NTOK * DIM, DD = (size_t)DIM * DIM;
    cvt_x_kernel<<<(int)(ND / 1024), 256>>>(x);
    cvt_w_kernel<<<dim3((int)(DD / 1024), 3), 256>>>(Wq, Wk, Wv);
    zero_l_kernel<<<NTOK / 1024, 1024>>>();

    qkv_mma<<<dim3(NTOK / 128, DIM / 128, 3), NTHR, SMEM_GEMM>>>(bq, bk, bv);
    scores_mma<<<dim3(NTOK / 128, NTOK / 128), NTHR, SMEM_GEMM>>>(ts);
    out_mma<<<dim3(NTOK / 128, DIM / 128), NTHR, SMEM_GEMM>>>(out);
}